// round 11
// baseline (speedup 1.0000x reference)
#include <cuda_runtime.h>
#include <stdint.h>
#include <math.h>

// ---------------------------------------------------------------------------
// QunatEncoderBlock: windowed attention + MLP with 8-bit fake quantization.
// Matmuls exact in int8->int32 via mma.sync m16n8k32 (legacy tensor-pipe path
// on sm_103a, ~375 MACs/cyc/SM ceiling; tcgen05 blocked by compute_103 PTX).
// Round 11: GEMM K-tile 64B -> 128B (3-stage cp.async, half the syncs,
// 64 mma/warp per barrier interval). Attention/LN/relpos unchanged.
// ---------------------------------------------------------------------------

#define DIMC   768
#define NHEAD  12
#define HDIM   64
#define MLPD   3072
#define WSZ    14
#define NTOK   196
#define NWIN   100
#define BHD    1200
#define PIX    16384
#define HH     64
#define WW     64
#define VPAD   208

// ------------------------------ scratch (device globals) -------------------
__device__ __align__(16) int8_t g_winq [PIX * DIMC];
__device__ __align__(16) int8_t g_wqkv [3 * DIMC * DIMC];
__device__ __align__(16) int8_t g_wproj[DIMC * DIMC];
__device__ __align__(16) int8_t g_wl1  [MLPD * DIMC];
__device__ __align__(16) int8_t g_wl2  [DIMC * MLPD];
__device__ __align__(16) int8_t g_q    [BHD * NTOK * HDIM];
__device__ __align__(16) int8_t g_k    [BHD * NTOK * HDIM];
__device__ __align__(16) int8_t g_vT   [BHD * HDIM * VPAD];
__device__ float  g_relh[BHD * NTOK * WSZ];
__device__ float  g_relw[BHD * NTOK * WSZ];
__device__ __align__(16) int8_t g_ov   [PIX * DIMC];
__device__ float  g_xres[(size_t)PIX * DIMC];
__device__ __align__(16) int8_t g_y    [PIX * DIMC];
__device__ __align__(16) int8_t g_hbuf [(size_t)PIX * MLPD];

__device__ __forceinline__ const int8_t* srcA(int id) {
    switch (id) { case 0: return g_winq; case 3: return g_ov;
                  case 4: return g_y;    default: return g_hbuf; }
}
__device__ __forceinline__ const int8_t* srcB(int id) {
    switch (id) { case 0: return g_wqkv; case 3: return g_wproj;
                  case 4: return g_wl1;  default: return g_wl2; }
}

// ------------------------------ helpers ------------------------------------
__device__ __forceinline__ int q8i(float x, float inv) {
    float r = rintf(x * inv);
    return (int)fminf(fmaxf(r, -128.0f), 127.0f);
}
__device__ __forceinline__ int8_t fq8m(float x, float inv) { return (int8_t)q8i(x, inv); }

__device__ __forceinline__ void mma_s8(int& c0, int& c1, int& c2, int& c3,
                                       int a0, int a1, int a2, int a3, int b0, int b1) {
    asm volatile(
        "mma.sync.aligned.m16n8k32.row.col.s32.s8.s8.s32 "
        "{%0,%1,%2,%3}, {%4,%5,%6,%7}, {%8,%9}, {%0,%1,%2,%3};"
        : "+r"(c0), "+r"(c1), "+r"(c2), "+r"(c3)
        : "r"(a0), "r"(a1), "r"(a2), "r"(a3), "r"(b0), "r"(b1));
}

#define CP_ASYNC16(dst, src) \
    asm volatile("cp.async.cg.shared.global [%0], [%1], 16;" :: "r"(dst), "l"(src))
#define CP_COMMIT() asm volatile("cp.async.commit_group;" ::: "memory")
#define CP_WAIT1()  asm volatile("cp.async.wait_group 1;" ::: "memory")

// ------------------------------ fused weight quantization ------------------
#define QW_N0 442368
#define QW_N1 147456
#define QW_N2 589824
#define QW_TOT (QW_N0 + QW_N1 + QW_N2 + QW_N2)

__global__ void __launch_bounds__(256)
quant_w_all(const float* __restrict__ w0, const float* __restrict__ w1,
            const float* __restrict__ w2, const float* __restrict__ w3,
            const float* __restrict__ ws) {
    int i = blockIdx.x * blockDim.x + threadIdx.x;
    if (i >= QW_TOT) return;
    const float* src; int li; float inv; int8_t* dst;
    if (i < QW_N0)                      { src = w0; li = i;                         inv = 1.0f / ws[0]; dst = g_wqkv; }
    else if (i < QW_N0 + QW_N1)         { src = w1; li = i - QW_N0;                 inv = 1.0f / ws[1]; dst = g_wproj; }
    else if (i < QW_N0 + QW_N1 + QW_N2) { src = w2; li = i - QW_N0 - QW_N1;         inv = 1.0f / ws[2]; dst = g_wl1; }
    else                                { src = w3; li = i - QW_N0 - QW_N1 - QW_N2; inv = 1.0f / ws[3]; dst = g_wl2; }
    float4 v = ((const float4*)src)[li];
    int p = (q8i(v.x, inv) & 255) | ((q8i(v.y, inv) & 255) << 8) |
            ((q8i(v.z, inv) & 255) << 16) | ((q8i(v.w, inv) & 255) << 24);
    ((int*)dst)[li] = p;
}

// ------------------------------ LN kernels (warp per token) ----------------
__device__ __forceinline__ void ln_row(const float* __restrict__ xp,
                                       const float* __restrict__ lw,
                                       const float* __restrict__ lb,
                                       float isc, int8_t* __restrict__ outp,
                                       int lane) {
    const float4* xp4 = (const float4*)xp;
    float4 v[6];
    float s = 0.f;
#pragma unroll
    for (int j = 0; j < 6; ++j) {
        v[j] = xp4[lane + 32 * j];
        s += v[j].x + v[j].y + v[j].z + v[j].w;
    }
#pragma unroll
    for (int o = 16; o > 0; o >>= 1) s += __shfl_xor_sync(~0u, s, o);
    float mu = s * (1.0f / DIMC);
    float sq = 0.f;
#pragma unroll
    for (int j = 0; j < 6; ++j) {
        float a = v[j].x - mu, b = v[j].y - mu, c = v[j].z - mu, d = v[j].w - mu;
        sq += a * a + b * b + c * c + d * d;
    }
#pragma unroll
    for (int o = 16; o > 0; o >>= 1) sq += __shfl_xor_sync(~0u, sq, o);
    float inv = 1.0f / sqrtf(sq * (1.0f / DIMC) + 1e-6f);
    const float4* lw4 = (const float4*)lw;
    const float4* lb4 = (const float4*)lb;
#pragma unroll
    for (int j = 0; j < 6; ++j) {
        float4 w4 = lw4[lane + 32 * j];
        float4 b4 = lb4[lane + 32 * j];
        int p = (q8i((v[j].x - mu) * inv * w4.x + b4.x, isc) & 255)
              | ((q8i((v[j].y - mu) * inv * w4.y + b4.y, isc) & 255) << 8)
              | ((q8i((v[j].z - mu) * inv * w4.z + b4.z, isc) & 255) << 16)
              | ((q8i((v[j].w - mu) * inv * w4.w + b4.w, isc) & 255) << 24);
        ((int*)outp)[lane + 32 * j] = p;
    }
}

__global__ void __launch_bounds__(256)
ln1_kernel(const float* __restrict__ x, const float* __restrict__ lw,
           const float* __restrict__ lb, const float* __restrict__ as) {
    int lane = threadIdx.x & 31, wid = threadIdx.x >> 5;
    int m = blockIdx.x * 8 + wid;
    ln_row(x + (size_t)m * DIMC, lw, lb, 1.0f / as[4], g_winq + (size_t)m * DIMC, lane);
}

__global__ void __launch_bounds__(256)
ln2_kernel(const float* __restrict__ lw, const float* __restrict__ lb,
           const float* __restrict__ as) {
    int lane = threadIdx.x & 31, wid = threadIdx.x >> 5;
    int m = blockIdx.x * 8 + wid;
    ln_row(g_xres + (size_t)m * DIMC, lw, lb, 1.0f / as[6], g_y + (size_t)m * DIMC, lane);
}

// ------------------------------ pad-token q/k/vT fill ----------------------
__global__ void __launch_bounds__(256)
pad_qkv_kernel(const float* __restrict__ qb, const float* __restrict__ as) {
    int wi = blockIdx.x;
    int rem = wi % 25, wr = rem / 5, wc = rem % 5;
    if (wr < 4 && wc < 4) return;
    __shared__ int sq[192], sk[192];
    __shared__ int8_t sv[768];
    int tid = threadIdx.x;
    float inv0 = 1.0f / as[0], inv1 = 1.0f / as[1], inv2 = 1.0f / as[2];
    for (int i = tid; i < 192; i += 256) {
        int n = i * 4;
        sq[i] = (q8i(qb[n], inv0) & 255) | ((q8i(qb[n+1], inv0) & 255) << 8)
              | ((q8i(qb[n+2], inv0) & 255) << 16) | ((q8i(qb[n+3], inv0) & 255) << 24);
        sk[i] = (q8i(qb[768+n], inv1) & 255) | ((q8i(qb[768+n+1], inv1) & 255) << 8)
              | ((q8i(qb[768+n+2], inv1) & 255) << 16) | ((q8i(qb[768+n+3], inv1) & 255) << 24);
    }
    for (int i = tid; i < 768; i += 256) sv[i] = fq8m(qb[1536 + i], inv2);
    __syncthreads();
    int lane = tid & 31, w = tid >> 5;
    for (int t = w; t < NTOK; t += 8) {
        int lr = t / WSZ, lc = t % WSZ;
        bool pad = (wr == 4 && lr >= 8) || (wc == 4 && lc >= 8);
        if (!pad) continue;
        for (int i = lane; i < 192; i += 32) {
            int head = i >> 4, di = i & 15;
            ((int*)(g_q + ((size_t)(wi * NHEAD + head) * NTOK + t) * HDIM))[di] = sq[i];
            ((int*)(g_k + ((size_t)(wi * NHEAD + head) * NTOK + t) * HDIM))[di] = sk[i];
        }
        for (int i = lane; i < 768; i += 32) {
            int head = i >> 6, d = i & 63;
            g_vT[((size_t)(wi * NHEAD + head) * HDIM + d) * VPAD + t] = sv[i];
        }
    }
}

// ------------------------------ decomposed rel-pos bias --------------------
__global__ void __launch_bounds__(224)
relpos_kernel(const float* __restrict__ rph, const float* __restrict__ rpw,
              const float* __restrict__ as) {
    __shared__ float shT[64 * 28];
    __shared__ float swT[64 * 28];
    int bh = blockIdx.x, t = threadIdx.x;
    for (int i = t; i < 27 * 64; i += 224) {
        int r = i >> 6, c = i & 63;
        shT[c * 28 + r] = rph[i];
        swT[c * 28 + r] = rpw[i];
    }
    __syncthreads();
    if (t >= NTOK) return;

    int hh = t / WSZ, ww2 = t % WSZ;
    const int* qi = (const int*)(g_q + ((size_t)bh * NTOK + t) * HDIM);
    float ah[WSZ], aw[WSZ];
#pragma unroll
    for (int kk = 0; kk < WSZ; ++kk) { ah[kk] = 0.f; aw[kk] = 0.f; }
#pragma unroll
    for (int j = 0; j < 16; ++j) {
        int packed = qi[j];
#pragma unroll
        for (int b = 0; b < 4; ++b) {
            int c = j * 4 + b;
            float qv = (float)((packed << (24 - 8 * b)) >> 24);
            const float* ph = &shT[c * 28 + hh + 13];
            const float* pw = &swT[c * 28 + ww2 + 13];
#pragma unroll
            for (int kk = 0; kk < WSZ; ++kk) {
                ah[kk] += qv * ph[-kk];
                aw[kk] += qv * pw[-kk];
            }
        }
    }
    float a0 = as[0];
    float* oh = g_relh + ((size_t)bh * NTOK + t) * WSZ;
    float* ow = g_relw + ((size_t)bh * NTOK + t) * WSZ;
#pragma unroll
    for (int kk = 0; kk < WSZ; ++kk) { oh[kk] = ah[kk] * a0; ow[kk] = aw[kk] * a0; }
}

// ------------------------------ fused attention -----------------------------
// 416 threads = 13 warps; each warp owns one 16-row strip (balanced).
// QK col tiles: 25 (200 >= 196). P cols [200,224) pre-zeroed for AV.
#define QSTR  20
#define SSTR  60
#define SQ_OFF  0
#define SK_OFF  (208 * QSTR)
#define SV_OFF  (SK_OFF + 200 * QSTR)
#define SS_OFF  (SV_OFF + 64 * SSTR)
#define ATT_SMEM ((SS_OFF + 208 * SSTR) * 4)

__global__ void __launch_bounds__(416)
attn_fused_kernel(const float* __restrict__ as) {
    extern __shared__ int sm[];
    int* sQ = sm + SQ_OFF; int* sK = sm + SK_OFF;
    int* sVT = sm + SV_OFF; int* sS = sm + SS_OFF;
    int bh = blockIdx.x, tid = threadIdx.x;
    int lane = tid & 31, wid = tid >> 5;
    int lrow = lane >> 2, lk = lane & 3;

    const int8_t* qg = g_q  + (size_t)bh * NTOK * HDIM;
    const int8_t* kg = g_k  + (size_t)bh * NTOK * HDIM;
    const int8_t* vg = g_vT + (size_t)bh * HDIM * VPAD;
    for (int idx = tid; idx < 208 * 4; idx += 416) {
        int row = idx >> 2, slot = idx & 3;
        int4 v = make_int4(0, 0, 0, 0);
        if (row < NTOK) v = *(const int4*)(qg + row * HDIM + slot * 16);
        *(int4*)&sQ[row * QSTR + slot * 4] = v;
    }
    for (int idx = tid; idx < 200 * 4; idx += 416) {
        int row = idx >> 2, slot = idx & 3;
        int4 v = make_int4(0, 0, 0, 0);
        if (row < NTOK) v = *(const int4*)(kg + row * HDIM + slot * 16);
        *(int4*)&sK[row * QSTR + slot * 4] = v;
    }
    for (int idx = tid; idx < 64 * 13; idx += 416) {
        int row = idx / 13, slot = idx % 13;
        *(int4*)&sVT[row * SSTR + slot * 4] = *(const int4*)(vg + row * VPAD + slot * 16);
    }
    for (int idx = tid; idx < 208 * 6; idx += 416)
        sS[(idx / 6) * SSTR + 50 + (idx % 6)] = 0;
    __syncthreads();

    float c_qk = 0.125f * as[0] * as[1];
    float inva3 = 1.0f / as[3];
    float c_av = as[3] * as[2];
    float inva5 = 1.0f / as[5];
    int wi = bh / NHEAD, head = bh % NHEAD;
    int wrem = wi % 25, wb = wi / 25, wwr = wrem / 5, wwc = wrem % 5;
    char* sSb = (char*)sS;

    {
        int s = wid;
        int m_lo = s * 16 + lrow, m_hi = m_lo + 8;
        int acc[25][4];
#pragma unroll
        for (int t = 0; t < 25; ++t) { acc[t][0]=acc[t][1]=acc[t][2]=acc[t][3]=0; }
#pragma unroll
        for (int kc = 0; kc < 2; ++kc) {
            int kb = kc * 8;
            int a0 = sQ[m_lo * QSTR + kb + lk];
            int a1 = sQ[m_hi * QSTR + kb + lk];
            int a2 = sQ[m_lo * QSTR + kb + 4 + lk];
            int a3 = sQ[m_hi * QSTR + kb + 4 + lk];
#pragma unroll
            for (int t = 0; t < 25; ++t) {
                int col = t * 8 + lrow;
                mma_s8(acc[t][0], acc[t][1], acc[t][2], acc[t][3],
                       a0, a1, a2, a3, sK[col * QSTR + kb + lk], sK[col * QSTR + kb + 4 + lk]);
            }
        }
        bool vlo = (m_lo < NTOK), vhi = (m_hi < NTOK);
        size_t blo = ((size_t)bh * NTOK + m_lo) * WSZ;
        size_t bhi = ((size_t)bh * NTOK + m_hi) * WSZ;
#pragma unroll
        for (int t = 0; t < 25; ++t) {
#pragma unroll
            for (int r = 0; r < 4; ++r) {
                int n = t * 8 + lk * 2 + (r & 1);
                bool vm = (r < 2) ? vlo : vhi;
                float f;
                if (n < NTOK && vm) {
                    size_t bb = (r < 2) ? blo : bhi;
                    f = (float)acc[t][r] * c_qk + g_relh[bb + n / WSZ] + g_relw[bb + n % WSZ];
                } else f = -1e30f;
                acc[t][r] = __float_as_int(f);
            }
        }
        float mx0 = -1e30f, mx1 = -1e30f;
#pragma unroll
        for (int t = 0; t < 25; ++t) {
            mx0 = fmaxf(mx0, fmaxf(__int_as_float(acc[t][0]), __int_as_float(acc[t][1])));
            mx1 = fmaxf(mx1, fmaxf(__int_as_float(acc[t][2]), __int_as_float(acc[t][3])));
        }
        mx0 = fmaxf(mx0, __shfl_xor_sync(~0u, mx0, 1)); mx0 = fmaxf(mx0, __shfl_xor_sync(~0u, mx0, 2));
        mx1 = fmaxf(mx1, __shfl_xor_sync(~0u, mx1, 1)); mx1 = fmaxf(mx1, __shfl_xor_sync(~0u, mx1, 2));
        float s0 = 0.f, s1 = 0.f;
#pragma unroll
        for (int t = 0; t < 25; ++t) {
            float e0 = __expf(__int_as_float(acc[t][0]) - mx0);
            float e1 = __expf(__int_as_float(acc[t][1]) - mx0);
            float e2 = __expf(__int_as_float(acc[t][2]) - mx1);
            float e3 = __expf(__int_as_float(acc[t][3]) - mx1);
            acc[t][0] = __float_as_int(e0); acc[t][1] = __float_as_int(e1);
            acc[t][2] = __float_as_int(e2); acc[t][3] = __float_as_int(e3);
            s0 += e0 + e1; s1 += e2 + e3;
        }
        s0 += __shfl_xor_sync(~0u, s0, 1); s0 += __shfl_xor_sync(~0u, s0, 2);
        s1 += __shfl_xor_sync(~0u, s1, 1); s1 += __shfl_xor_sync(~0u, s1, 2);
        float r0 = inva3 / s0, r1 = inva3 / s1;
#pragma unroll
        for (int t = 0; t < 25; ++t) {
            int v00 = q8i(__int_as_float(acc[t][0]), r0);
            int v01 = q8i(__int_as_float(acc[t][1]), r0);
            int v10 = q8i(__int_as_float(acc[t][2]), r1);
            int v11 = q8i(__int_as_float(acc[t][3]), r1);
            *(unsigned short*)(sSb + m_lo * (SSTR * 4) + t * 8 + lk * 2) =
                (unsigned short)((v00 & 0xFF) | ((v01 & 0xFF) << 8));
            *(unsigned short*)(sSb + m_hi * (SSTR * 4) + t * 8 + lk * 2) =
                (unsigned short)((v10 & 0xFF) | ((v11 & 0xFF) << 8));
        }
        __syncwarp();
        int oacc[8][4];
#pragma unroll
        for (int j = 0; j < 8; ++j) { oacc[j][0]=oacc[j][1]=oacc[j][2]=oacc[j][3]=0; }
#pragma unroll
        for (int kc = 0; kc < 7; ++kc) {
            int kb = kc * 8;
            int a0 = sS[m_lo * SSTR + kb + lk];
            int a1 = sS[m_hi * SSTR + kb + lk];
            int a2 = sS[m_lo * SSTR + kb + 4 + lk];
            int a3 = sS[m_hi * SSTR + kb + 4 + lk];
#pragma unroll
            for (int j = 0; j < 8; ++j) {
                int col = j * 8 + lrow;
                mma_s8(oacc[j][0], oacc[j][1], oacc[j][2], oacc[j][3],
                       a0, a1, a2, a3, sVT[col * SSTR + kb + lk], sVT[col * SSTR + kb + 4 + lk]);
            }
        }
        int rlo = wwr * WSZ + m_lo / WSZ, clo = wwc * WSZ + m_lo % WSZ;
        int rhi = wwr * WSZ + m_hi / WSZ, chi = wwc * WSZ + m_hi % WSZ;
        bool oklo = vlo && rlo < HH && clo < WW;
        bool okhi = vhi && rhi < HH && chi < WW;
        size_t plo = (((size_t)(wb * HH + rlo)) * WW + clo) * DIMC + head * HDIM;
        size_t phi = (((size_t)(wb * HH + rhi)) * WW + chi) * DIMC + head * HDIM;
#pragma unroll
        for (int j = 0; j < 8; ++j) {
            int n = j * 8 + lk * 2;
            if (oklo) {
                int v0 = q8i((float)oacc[j][0] * c_av, inva5);
                int v1 = q8i((float)oacc[j][1] * c_av, inva5);
                *(unsigned short*)(g_ov + plo + n) =
                    (unsigned short)((v0 & 0xFF) | ((v1 & 0xFF) << 8));
            }
            if (okhi) {
                int v0 = q8i((float)oacc[j][2] * c_av, inva5);
                int v1 = q8i((float)oacc[j][3] * c_av, inva5);
                *(unsigned short*)(g_ov + phi + n) =
                    (unsigned short)((v0 & 0xFF) | ((v1 & 0xFF) << 8));
            }
        }
    }
}

// ------------------------------ int8 IMMA GEMM (cp.async, 3-stage, 128B K) --
// Dims: M,N multiples of 128; K multiple of 128 elems -> no bounds checks.
// Per stage: A 128x144B + B 128x144B = 36864 B; 3 stages = 110592 B.
// Row stride 36 ints: (r*36+lk) mod 32 = r*4+lk -> conflict-free frags.
#define GEMM_SMEM 110592

template <typename Epi>
__global__ void __launch_bounds__(256)
gemm_i8(int aid, int bid, int Kints, Epi epi) {
    extern __shared__ int gsm[];
    const int8_t* Ab = srcA(aid);
    const int8_t* Bb = srcB(bid);
    int bm = blockIdx.y * 128, bn = blockIdx.x * 128;
    int tid = threadIdx.x;
    int lane = tid & 31, wid = tid >> 5;
    int wm = wid >> 2, wn = wid & 3;
    int lrow = lane >> 2, lk = lane & 3;
    int srow = tid >> 1;          // 0..127
    int shalf = tid & 1;          // 0..1 (64B half of the 128B row)

    uint32_t sbase = (uint32_t)__cvta_generic_to_shared(gsm);
    size_t Kbytes = (size_t)Kints * 4;
    const int8_t* Abase = Ab + (size_t)(bm + srow) * Kbytes + shalf * 64;
    const int8_t* Bbase = Bb + (size_t)(bn + srow) * Kbytes + shalf * 64;
    uint32_t a_off = sbase + srow * 144 + shalf * 64;
    uint32_t b_off = sbase + 18432 + srow * 144 + shalf * 64;

    int acc[4][4][4];
#pragma unroll
    for (int i = 0; i < 4; ++i)
#pragma unroll
        for (int j = 0; j < 4; ++j)
#pragma unroll
            for (int r = 0; r < 4; ++r) acc[i][j][r] = 0;

    auto load_tile = [&](int kt, int stg) {
        const int8_t* ga = Abase + kt * 128;
        const int8_t* gb = Bbase + kt * 128;
        uint32_t ao = a_off + stg * 36864;
        uint32_t bo = b_off + stg * 36864;
#pragma unroll
        for (int j = 0; j < 4; ++j) CP_ASYNC16(ao + j * 16, ga + j * 16);
#pragma unroll
        for (int j = 0; j < 4; ++j) CP_ASYNC16(bo + j * 16, gb + j * 16);
        CP_COMMIT();
    };

    int nk = Kints >> 5;          // 128B tiles
    load_tile(0, 0);
    load_tile(1, 1);

    for (int kt = 0; kt < nk; ++kt) {
        CP_WAIT1();
        __syncthreads();
        int cur = kt - (kt / 3) * 3;
        const int* sAc = gsm + cur * 9216;
        const int* sBc = gsm + cur * 9216 + 4608;
#pragma unroll
        for (int kc = 0; kc < 4; ++kc) {
            int kb = kc * 8;
            int b0[4], b1[4];
#pragma unroll
            for (int j = 0; j < 4; ++j) {
                int col = wn * 32 + j * 8 + lrow;
                b0[j] = sBc[col * 36 + kb + lk];
                b1[j] = sBc[col * 36 + kb + 4 + lk];
            }
#pragma unroll
            for (int i = 0; i < 4; ++i) {
                int r0 = wm * 64 + i * 16 + lrow;
                int a0 = sAc[r0 * 36 + kb + lk];
                int a1 = sAc[(r0 + 8) * 36 + kb + lk];
                int a2 = sAc[r0 * 36 + kb + 4 + lk];
                int a3 = sAc[(r0 + 8) * 36 + kb + 4 + lk];
#pragma unroll
                for (int j = 0; j < 4; ++j)
                    mma_s8(acc[i][j][0], acc[i][j][1], acc[i][j][2], acc[i][j][3],
                           a0, a1, a2, a3, b0[j], b1[j]);
            }
        }
        if (kt + 2 < nk) {
            int stg = kt + 2;
            stg -= (stg / 3) * 3;
            load_tile(kt + 2, stg);
        }
    }

    epi.prep();
#pragma unroll
    for (int i = 0; i < 4; ++i) {
        int m0 = bm + wm * 64 + i * 16 + lrow;
#pragma unroll
        for (int j = 0; j < 4; ++j) {
            int n0 = bn + wn * 32 + j * 8 + lk * 2;
            epi(acc[i][j][0], m0, n0);
            epi(acc[i][j][1], m0, n0 + 1);
            epi(acc[i][j][2], m0 + 8, n0);
            epi(acc[i][j][3], m0 + 8, n0 + 1);
        }
    }
}

// ------------------------------ GEMM epilogues ------------------------------
struct EpiQKV {
    const float* as; const float* ws; const float* qb;
    float s1, inv0, inv1, inv2;
    __device__ void prep() {
        s1 = as[4] * ws[0];
        inv0 = 1.0f / as[0]; inv1 = 1.0f / as[1]; inv2 = 1.0f / as[2];
    }
    __device__ void operator()(int acc, int m, int n) const {
        float f = (float)acc * s1 + qb[n];
        int qi = (n >= 1536) ? 2 : (n >= 768 ? 1 : 0);
        int rem = n - qi * 768;
        int head = rem >> 6, d = rem & 63;
        int b = m >> 12, r = (m >> 6) & 63, c = m & 63;
        int wr = r / WSZ, lr = r - wr * WSZ;
        int wc = c / WSZ, lc = c - wc * WSZ;
        int wi = b * 25 + wr * 5 + wc;
        int t = lr * WSZ + lc;
        int bh = wi * NHEAD + head;
        if (qi == 0)      g_q [((size_t)bh * NTOK + t) * HDIM + d] = fq8m(f, inv0);
        else if (qi == 1) g_k [((size_t)bh * NTOK + t) * HDIM + d] = fq8m(f, inv1);
        else              g_vT[((size_t)bh * HDIM + d) * VPAD + t] = fq8m(f, inv2);
    }
};
struct EpiProj {
    const float* as; const float* ws; const float* pb; const float* x;
    float s1;
    __device__ void prep() { s1 = as[5] * ws[1]; }
    __device__ void operator()(int acc, int m, int n) const {
        size_t idx = (size_t)m * DIMC + n;
        g_xres[idx] = x[idx] + (float)acc * s1 + pb[n];
    }
};
struct EpiL1 {
    const float* as; const float* ws; const float* lb;
    float s1, inv7;
    __device__ void prep() { s1 = as[6] * ws[2]; inv7 = 1.0f / as[7]; }
    __device__ void operator()(int acc, int m, int n) const {
        float f = (float)acc * s1 + lb[n];
        float xx = f * 0.70710678118654752f;
        float ax = fabsf(xx);
        float t = __fdividef(1.0f, 1.0f + 0.3275911f * ax);
        float poly = t * (0.254829592f + t * (-0.284496736f + t * (1.421413741f +
                     t * (-1.453152027f + t * 1.061405429f))));
        float erfv = 1.0f - poly * __expf(-xx * xx);
        erfv = copysignf(erfv, xx);
        float g = 0.5f * f * (1.0f + erfv);
        g_hbuf[(size_t)m * MLPD + n] = fq8m(g, inv7);
    }
};
struct EpiL2 {
    const float* as; const float* ws; const float* lb; float* out;
    float s1;
    __device__ void prep() { s1 = as[7] * ws[3]; }
    __device__ void operator()(int acc, int m, int n) const {
        size_t idx = (size_t)m * DIMC + n;
        out[idx] = g_xres[idx] + (float)acc * s1 + lb[n];
    }
};

// ------------------------------ launch --------------------------------------
extern "C" void kernel_launch(void* const* d_in, const int* in_sizes, int n_in,
                              void* d_out, int out_size) {
    const float* x      = (const float*)d_in[0];
    const float* ln1_w  = (const float*)d_in[1];
    const float* ln1_b  = (const float*)d_in[2];
    const float* ln2_w  = (const float*)d_in[3];
    const float* ln2_b  = (const float*)d_in[4];
    const float* qkv_w  = (const float*)d_in[5];
    const float* qkv_b  = (const float*)d_in[6];
    const float* proj_w = (const float*)d_in[7];
    const float* proj_b = (const float*)d_in[8];
    const float* lin1_w = (const float*)d_in[9];
    const float* lin1_b = (const float*)d_in[10];
    const float* lin2_w = (const float*)d_in[11];
    const float* lin2_b = (const float*)d_in[12];
    const float* rph    = (const float*)d_in[13];
    const float* rpw    = (const float*)d_in[14];
    const float* asc    = (const float*)d_in[15];
    const float* wsc    = (const float*)d_in[16];
    float* out = (float*)d_out;

    cudaFuncSetAttribute(attn_fused_kernel, cudaFuncAttributeMaxDynamicSharedMemorySize, ATT_SMEM);
    cudaFuncSetAttribute(gemm_i8<EpiQKV>,  cudaFuncAttributeMaxDynamicSharedMemorySize, GEMM_SMEM);
    cudaFuncSetAttribute(gemm_i8<EpiProj>, cudaFuncAttributeMaxDynamicSharedMemorySize, GEMM_SMEM);
    cudaFuncSetAttribute(gemm_i8<EpiL1>,   cudaFuncAttributeMaxDynamicSharedMemorySize, GEMM_SMEM);
    cudaFuncSetAttribute(gemm_i8<EpiL2>,   cudaFuncAttributeMaxDynamicSharedMemorySize, GEMM_SMEM);

    quant_w_all<<<(QW_TOT + 255) / 256, 256>>>(qkv_w, proj_w, lin1_w, lin2_w, wsc);

    ln1_kernel<<<PIX / 8, 256>>>(x, ln1_w, ln1_b, asc);
    pad_qkv_kernel<<<NWIN, 256>>>(qkv_b, asc);

    gemm_i8<EpiQKV><<<dim3(18, 128), 256, GEMM_SMEM>>>(0, 0, DIMC / 4,
                                                       EpiQKV{asc, wsc, qkv_b});

    relpos_kernel<<<BHD, 224>>>(rph, rpw, asc);
    attn_fused_kernel<<<BHD, 416, ATT_SMEM>>>(asc);

    gemm_i8<EpiProj><<<dim3(6, 128), 256, GEMM_SMEM>>>(3, 3, DIMC / 4,
                                                       EpiProj{asc, wsc, proj_b, x});

    ln2_kernel<<<PIX / 8, 256>>>(ln2_w, ln2_b, asc);

    gemm_i8<EpiL1><<<dim3(24, 128), 256, GEMM_SMEM>>>(4, 4, DIMC / 4,
                                                      EpiL1{asc, wsc, lin1_b});
    gemm_i8<EpiL2><<<dim3(6, 128), 256, GEMM_SMEM>>>(5, 5, MLPD / 4,
                                                     EpiL2{asc, wsc, lin2_b, out});
}

// round 12
// speedup vs baseline: 1.0547x; 1.0547x over previous
#include <cuda_runtime.h>
#include <stdint.h>
#include <math.h>

// ---------------------------------------------------------------------------
// QunatEncoderBlock: windowed attention + MLP with 8-bit fake quantization.
// Matmuls exact in int8->int32 via mma.sync m16n8k32 (legacy tensor-pipe path
// on sm_103a; tcgen05 blocked by compute_103 PTX target).
// Round 12: round-10 GEMM body (64B K-tiles) + 4-stage cp.async pipeline with
// wait_group 2 (two tile-loads in flight at every barrier).
// ---------------------------------------------------------------------------

#define DIMC   768
#define NHEAD  12
#define HDIM   64
#define MLPD   3072
#define WSZ    14
#define NTOK   196
#define NWIN   100
#define BHD    1200
#define PIX    16384
#define HH     64
#define WW     64
#define VPAD   208

// ------------------------------ scratch (device globals) -------------------
__device__ __align__(16) int8_t g_winq [PIX * DIMC];
__device__ __align__(16) int8_t g_wqkv [3 * DIMC * DIMC];
__device__ __align__(16) int8_t g_wproj[DIMC * DIMC];
__device__ __align__(16) int8_t g_wl1  [MLPD * DIMC];
__device__ __align__(16) int8_t g_wl2  [DIMC * MLPD];
__device__ __align__(16) int8_t g_q    [BHD * NTOK * HDIM];
__device__ __align__(16) int8_t g_k    [BHD * NTOK * HDIM];
__device__ __align__(16) int8_t g_vT   [BHD * HDIM * VPAD];
__device__ float  g_relh[BHD * NTOK * WSZ];
__device__ float  g_relw[BHD * NTOK * WSZ];
__device__ __align__(16) int8_t g_ov   [PIX * DIMC];
__device__ float  g_xres[(size_t)PIX * DIMC];
__device__ __align__(16) int8_t g_y    [PIX * DIMC];
__device__ __align__(16) int8_t g_hbuf [(size_t)PIX * MLPD];

__device__ __forceinline__ const int8_t* srcA(int id) {
    switch (id) { case 0: return g_winq; case 3: return g_ov;
                  case 4: return g_y;    default: return g_hbuf; }
}
__device__ __forceinline__ const int8_t* srcB(int id) {
    switch (id) { case 0: return g_wqkv; case 3: return g_wproj;
                  case 4: return g_wl1;  default: return g_wl2; }
}

// ------------------------------ helpers ------------------------------------
__device__ __forceinline__ int q8i(float x, float inv) {
    float r = rintf(x * inv);
    return (int)fminf(fmaxf(r, -128.0f), 127.0f);
}
__device__ __forceinline__ int8_t fq8m(float x, float inv) { return (int8_t)q8i(x, inv); }

__device__ __forceinline__ void mma_s8(int& c0, int& c1, int& c2, int& c3,
                                       int a0, int a1, int a2, int a3, int b0, int b1) {
    asm volatile(
        "mma.sync.aligned.m16n8k32.row.col.s32.s8.s8.s32 "
        "{%0,%1,%2,%3}, {%4,%5,%6,%7}, {%8,%9}, {%0,%1,%2,%3};"
        : "+r"(c0), "+r"(c1), "+r"(c2), "+r"(c3)
        : "r"(a0), "r"(a1), "r"(a2), "r"(a3), "r"(b0), "r"(b1));
}

#define CP_ASYNC16(dst, src) \
    asm volatile("cp.async.cg.shared.global [%0], [%1], 16;" :: "r"(dst), "l"(src))
#define CP_COMMIT() asm volatile("cp.async.commit_group;" ::: "memory")
#define CP_WAIT2()  asm volatile("cp.async.wait_group 2;" ::: "memory")

// ------------------------------ fused weight quantization ------------------
#define QW_N0 442368
#define QW_N1 147456
#define QW_N2 589824
#define QW_TOT (QW_N0 + QW_N1 + QW_N2 + QW_N2)

__global__ void __launch_bounds__(256)
quant_w_all(const float* __restrict__ w0, const float* __restrict__ w1,
            const float* __restrict__ w2, const float* __restrict__ w3,
            const float* __restrict__ ws) {
    int i = blockIdx.x * blockDim.x + threadIdx.x;
    if (i >= QW_TOT) return;
    const float* src; int li; float inv; int8_t* dst;
    if (i < QW_N0)                      { src = w0; li = i;                         inv = 1.0f / ws[0]; dst = g_wqkv; }
    else if (i < QW_N0 + QW_N1)         { src = w1; li = i - QW_N0;                 inv = 1.0f / ws[1]; dst = g_wproj; }
    else if (i < QW_N0 + QW_N1 + QW_N2) { src = w2; li = i - QW_N0 - QW_N1;         inv = 1.0f / ws[2]; dst = g_wl1; }
    else                                { src = w3; li = i - QW_N0 - QW_N1 - QW_N2; inv = 1.0f / ws[3]; dst = g_wl2; }
    float4 v = ((const float4*)src)[li];
    int p = (q8i(v.x, inv) & 255) | ((q8i(v.y, inv) & 255) << 8) |
            ((q8i(v.z, inv) & 255) << 16) | ((q8i(v.w, inv) & 255) << 24);
    ((int*)dst)[li] = p;
}

// ------------------------------ LN kernels (warp per token) ----------------
__device__ __forceinline__ void ln_row(const float* __restrict__ xp,
                                       const float* __restrict__ lw,
                                       const float* __restrict__ lb,
                                       float isc, int8_t* __restrict__ outp,
                                       int lane) {
    const float4* xp4 = (const float4*)xp;
    float4 v[6];
    float s = 0.f;
#pragma unroll
    for (int j = 0; j < 6; ++j) {
        v[j] = xp4[lane + 32 * j];
        s += v[j].x + v[j].y + v[j].z + v[j].w;
    }
#pragma unroll
    for (int o = 16; o > 0; o >>= 1) s += __shfl_xor_sync(~0u, s, o);
    float mu = s * (1.0f / DIMC);
    float sq = 0.f;
#pragma unroll
    for (int j = 0; j < 6; ++j) {
        float a = v[j].x - mu, b = v[j].y - mu, c = v[j].z - mu, d = v[j].w - mu;
        sq += a * a + b * b + c * c + d * d;
    }
#pragma unroll
    for (int o = 16; o > 0; o >>= 1) sq += __shfl_xor_sync(~0u, sq, o);
    float inv = 1.0f / sqrtf(sq * (1.0f / DIMC) + 1e-6f);
    const float4* lw4 = (const float4*)lw;
    const float4* lb4 = (const float4*)lb;
#pragma unroll
    for (int j = 0; j < 6; ++j) {
        float4 w4 = lw4[lane + 32 * j];
        float4 b4 = lb4[lane + 32 * j];
        int p = (q8i((v[j].x - mu) * inv * w4.x + b4.x, isc) & 255)
              | ((q8i((v[j].y - mu) * inv * w4.y + b4.y, isc) & 255) << 8)
              | ((q8i((v[j].z - mu) * inv * w4.z + b4.z, isc) & 255) << 16)
              | ((q8i((v[j].w - mu) * inv * w4.w + b4.w, isc) & 255) << 24);
        ((int*)outp)[lane + 32 * j] = p;
    }
}

__global__ void __launch_bounds__(256)
ln1_kernel(const float* __restrict__ x, const float* __restrict__ lw,
           const float* __restrict__ lb, const float* __restrict__ as) {
    int lane = threadIdx.x & 31, wid = threadIdx.x >> 5;
    int m = blockIdx.x * 8 + wid;
    ln_row(x + (size_t)m * DIMC, lw, lb, 1.0f / as[4], g_winq + (size_t)m * DIMC, lane);
}

__global__ void __launch_bounds__(256)
ln2_kernel(const float* __restrict__ lw, const float* __restrict__ lb,
           const float* __restrict__ as) {
    int lane = threadIdx.x & 31, wid = threadIdx.x >> 5;
    int m = blockIdx.x * 8 + wid;
    ln_row(g_xres + (size_t)m * DIMC, lw, lb, 1.0f / as[6], g_y + (size_t)m * DIMC, lane);
}

// ------------------------------ pad-token q/k/vT fill ----------------------
__global__ void __launch_bounds__(256)
pad_qkv_kernel(const float* __restrict__ qb, const float* __restrict__ as) {
    int wi = blockIdx.x;
    int rem = wi % 25, wr = rem / 5, wc = rem % 5;
    if (wr < 4 && wc < 4) return;
    __shared__ int sq[192], sk[192];
    __shared__ int8_t sv[768];
    int tid = threadIdx.x;
    float inv0 = 1.0f / as[0], inv1 = 1.0f / as[1], inv2 = 1.0f / as[2];
    for (int i = tid; i < 192; i += 256) {
        int n = i * 4;
        sq[i] = (q8i(qb[n], inv0) & 255) | ((q8i(qb[n+1], inv0) & 255) << 8)
              | ((q8i(qb[n+2], inv0) & 255) << 16) | ((q8i(qb[n+3], inv0) & 255) << 24);
        sk[i] = (q8i(qb[768+n], inv1) & 255) | ((q8i(qb[768+n+1], inv1) & 255) << 8)
              | ((q8i(qb[768+n+2], inv1) & 255) << 16) | ((q8i(qb[768+n+3], inv1) & 255) << 24);
    }
    for (int i = tid; i < 768; i += 256) sv[i] = fq8m(qb[1536 + i], inv2);
    __syncthreads();
    int lane = tid & 31, w = tid >> 5;
    for (int t = w; t < NTOK; t += 8) {
        int lr = t / WSZ, lc = t % WSZ;
        bool pad = (wr == 4 && lr >= 8) || (wc == 4 && lc >= 8);
        if (!pad) continue;
        for (int i = lane; i < 192; i += 32) {
            int head = i >> 4, di = i & 15;
            ((int*)(g_q + ((size_t)(wi * NHEAD + head) * NTOK + t) * HDIM))[di] = sq[i];
            ((int*)(g_k + ((size_t)(wi * NHEAD + head) * NTOK + t) * HDIM))[di] = sk[i];
        }
        for (int i = lane; i < 768; i += 32) {
            int head = i >> 6, d = i & 63;
            g_vT[((size_t)(wi * NHEAD + head) * HDIM + d) * VPAD + t] = sv[i];
        }
    }
}

// ------------------------------ decomposed rel-pos bias --------------------
__global__ void __launch_bounds__(224)
relpos_kernel(const float* __restrict__ rph, const float* __restrict__ rpw,
              const float* __restrict__ as) {
    __shared__ float shT[64 * 28];
    __shared__ float swT[64 * 28];
    int bh = blockIdx.x, t = threadIdx.x;
    for (int i = t; i < 27 * 64; i += 224) {
        int r = i >> 6, c = i & 63;
        shT[c * 28 + r] = rph[i];
        swT[c * 28 + r] = rpw[i];
    }
    __syncthreads();
    if (t >= NTOK) return;

    int hh = t / WSZ, ww2 = t % WSZ;
    const int* qi = (const int*)(g_q + ((size_t)bh * NTOK + t) * HDIM);
    float ah[WSZ], aw[WSZ];
#pragma unroll
    for (int kk = 0; kk < WSZ; ++kk) { ah[kk] = 0.f; aw[kk] = 0.f; }
#pragma unroll
    for (int j = 0; j < 16; ++j) {
        int packed = qi[j];
#pragma unroll
        for (int b = 0; b < 4; ++b) {
            int c = j * 4 + b;
            float qv = (float)((packed << (24 - 8 * b)) >> 24);
            const float* ph = &shT[c * 28 + hh + 13];
            const float* pw = &swT[c * 28 + ww2 + 13];
#pragma unroll
            for (int kk = 0; kk < WSZ; ++kk) {
                ah[kk] += qv * ph[-kk];
                aw[kk] += qv * pw[-kk];
            }
        }
    }
    float a0 = as[0];
    float* oh = g_relh + ((size_t)bh * NTOK + t) * WSZ;
    float* ow = g_relw + ((size_t)bh * NTOK + t) * WSZ;
#pragma unroll
    for (int kk = 0; kk < WSZ; ++kk) { oh[kk] = ah[kk] * a0; ow[kk] = aw[kk] * a0; }
}

// ------------------------------ fused attention -----------------------------
// 416 threads = 13 warps; each warp owns one 16-row strip (balanced).
// QK col tiles: 25 (200 >= 196). P cols [200,224) pre-zeroed for AV.
#define QSTR  20
#define SSTR  60
#define SQ_OFF  0
#define SK_OFF  (208 * QSTR)
#define SV_OFF  (SK_OFF + 200 * QSTR)
#define SS_OFF  (SV_OFF + 64 * SSTR)
#define ATT_SMEM ((SS_OFF + 208 * SSTR) * 4)

__global__ void __launch_bounds__(416)
attn_fused_kernel(const float* __restrict__ as) {
    extern __shared__ int sm[];
    int* sQ = sm + SQ_OFF; int* sK = sm + SK_OFF;
    int* sVT = sm + SV_OFF; int* sS = sm + SS_OFF;
    int bh = blockIdx.x, tid = threadIdx.x;
    int lane = tid & 31, wid = tid >> 5;
    int lrow = lane >> 2, lk = lane & 3;

    const int8_t* qg = g_q  + (size_t)bh * NTOK * HDIM;
    const int8_t* kg = g_k  + (size_t)bh * NTOK * HDIM;
    const int8_t* vg = g_vT + (size_t)bh * HDIM * VPAD;
    for (int idx = tid; idx < 208 * 4; idx += 416) {
        int row = idx >> 2, slot = idx & 3;
        int4 v = make_int4(0, 0, 0, 0);
        if (row < NTOK) v = *(const int4*)(qg + row * HDIM + slot * 16);
        *(int4*)&sQ[row * QSTR + slot * 4] = v;
    }
    for (int idx = tid; idx < 200 * 4; idx += 416) {
        int row = idx >> 2, slot = idx & 3;
        int4 v = make_int4(0, 0, 0, 0);
        if (row < NTOK) v = *(const int4*)(kg + row * HDIM + slot * 16);
        *(int4*)&sK[row * QSTR + slot * 4] = v;
    }
    for (int idx = tid; idx < 64 * 13; idx += 416) {
        int row = idx / 13, slot = idx % 13;
        *(int4*)&sVT[row * SSTR + slot * 4] = *(const int4*)(vg + row * VPAD + slot * 16);
    }
    for (int idx = tid; idx < 208 * 6; idx += 416)
        sS[(idx / 6) * SSTR + 50 + (idx % 6)] = 0;
    __syncthreads();

    float c_qk = 0.125f * as[0] * as[1];
    float inva3 = 1.0f / as[3];
    float c_av = as[3] * as[2];
    float inva5 = 1.0f / as[5];
    int wi = bh / NHEAD, head = bh % NHEAD;
    int wrem = wi % 25, wb = wi / 25, wwr = wrem / 5, wwc = wrem % 5;
    char* sSb = (char*)sS;

    {
        int s = wid;
        int m_lo = s * 16 + lrow, m_hi = m_lo + 8;
        int acc[25][4];
#pragma unroll
        for (int t = 0; t < 25; ++t) { acc[t][0]=acc[t][1]=acc[t][2]=acc[t][3]=0; }
#pragma unroll
        for (int kc = 0; kc < 2; ++kc) {
            int kb = kc * 8;
            int a0 = sQ[m_lo * QSTR + kb + lk];
            int a1 = sQ[m_hi * QSTR + kb + lk];
            int a2 = sQ[m_lo * QSTR + kb + 4 + lk];
            int a3 = sQ[m_hi * QSTR + kb + 4 + lk];
#pragma unroll
            for (int t = 0; t < 25; ++t) {
                int col = t * 8 + lrow;
                mma_s8(acc[t][0], acc[t][1], acc[t][2], acc[t][3],
                       a0, a1, a2, a3, sK[col * QSTR + kb + lk], sK[col * QSTR + kb + 4 + lk]);
            }
        }
        bool vlo = (m_lo < NTOK), vhi = (m_hi < NTOK);
        size_t blo = ((size_t)bh * NTOK + m_lo) * WSZ;
        size_t bhi = ((size_t)bh * NTOK + m_hi) * WSZ;
#pragma unroll
        for (int t = 0; t < 25; ++t) {
#pragma unroll
            for (int r = 0; r < 4; ++r) {
                int n = t * 8 + lk * 2 + (r & 1);
                bool vm = (r < 2) ? vlo : vhi;
                float f;
                if (n < NTOK && vm) {
                    size_t bb = (r < 2) ? blo : bhi;
                    f = (float)acc[t][r] * c_qk + g_relh[bb + n / WSZ] + g_relw[bb + n % WSZ];
                } else f = -1e30f;
                acc[t][r] = __float_as_int(f);
            }
        }
        float mx0 = -1e30f, mx1 = -1e30f;
#pragma unroll
        for (int t = 0; t < 25; ++t) {
            mx0 = fmaxf(mx0, fmaxf(__int_as_float(acc[t][0]), __int_as_float(acc[t][1])));
            mx1 = fmaxf(mx1, fmaxf(__int_as_float(acc[t][2]), __int_as_float(acc[t][3])));
        }
        mx0 = fmaxf(mx0, __shfl_xor_sync(~0u, mx0, 1)); mx0 = fmaxf(mx0, __shfl_xor_sync(~0u, mx0, 2));
        mx1 = fmaxf(mx1, __shfl_xor_sync(~0u, mx1, 1)); mx1 = fmaxf(mx1, __shfl_xor_sync(~0u, mx1, 2));
        float s0 = 0.f, s1 = 0.f;
#pragma unroll
        for (int t = 0; t < 25; ++t) {
            float e0 = __expf(__int_as_float(acc[t][0]) - mx0);
            float e1 = __expf(__int_as_float(acc[t][1]) - mx0);
            float e2 = __expf(__int_as_float(acc[t][2]) - mx1);
            float e3 = __expf(__int_as_float(acc[t][3]) - mx1);
            acc[t][0] = __float_as_int(e0); acc[t][1] = __float_as_int(e1);
            acc[t][2] = __float_as_int(e2); acc[t][3] = __float_as_int(e3);
            s0 += e0 + e1; s1 += e2 + e3;
        }
        s0 += __shfl_xor_sync(~0u, s0, 1); s0 += __shfl_xor_sync(~0u, s0, 2);
        s1 += __shfl_xor_sync(~0u, s1, 1); s1 += __shfl_xor_sync(~0u, s1, 2);
        float r0 = inva3 / s0, r1 = inva3 / s1;
#pragma unroll
        for (int t = 0; t < 25; ++t) {
            int v00 = q8i(__int_as_float(acc[t][0]), r0);
            int v01 = q8i(__int_as_float(acc[t][1]), r0);
            int v10 = q8i(__int_as_float(acc[t][2]), r1);
            int v11 = q8i(__int_as_float(acc[t][3]), r1);
            *(unsigned short*)(sSb + m_lo * (SSTR * 4) + t * 8 + lk * 2) =
                (unsigned short)((v00 & 0xFF) | ((v01 & 0xFF) << 8));
            *(unsigned short*)(sSb + m_hi * (SSTR * 4) + t * 8 + lk * 2) =
                (unsigned short)((v10 & 0xFF) | ((v11 & 0xFF) << 8));
        }
        __syncwarp();
        int oacc[8][4];
#pragma unroll
        for (int j = 0; j < 8; ++j) { oacc[j][0]=oacc[j][1]=oacc[j][2]=oacc[j][3]=0; }
#pragma unroll
        for (int kc = 0; kc < 7; ++kc) {
            int kb = kc * 8;
            int a0 = sS[m_lo * SSTR + kb + lk];
            int a1 = sS[m_hi * SSTR + kb + lk];
            int a2 = sS[m_lo * SSTR + kb + 4 + lk];
            int a3 = sS[m_hi * SSTR + kb + 4 + lk];
#pragma unroll
            for (int j = 0; j < 8; ++j) {
                int col = j * 8 + lrow;
                mma_s8(oacc[j][0], oacc[j][1], oacc[j][2], oacc[j][3],
                       a0, a1, a2, a3, sVT[col * SSTR + kb + lk], sVT[col * SSTR + kb + 4 + lk]);
            }
        }
        int rlo = wwr * WSZ + m_lo / WSZ, clo = wwc * WSZ + m_lo % WSZ;
        int rhi = wwr * WSZ + m_hi / WSZ, chi = wwc * WSZ + m_hi % WSZ;
        bool oklo = vlo && rlo < HH && clo < WW;
        bool okhi = vhi && rhi < HH && chi < WW;
        size_t plo = (((size_t)(wb * HH + rlo)) * WW + clo) * DIMC + head * HDIM;
        size_t phi = (((size_t)(wb * HH + rhi)) * WW + chi) * DIMC + head * HDIM;
#pragma unroll
        for (int j = 0; j < 8; ++j) {
            int n = j * 8 + lk * 2;
            if (oklo) {
                int v0 = q8i((float)oacc[j][0] * c_av, inva5);
                int v1 = q8i((float)oacc[j][1] * c_av, inva5);
                *(unsigned short*)(g_ov + plo + n) =
                    (unsigned short)((v0 & 0xFF) | ((v1 & 0xFF) << 8));
            }
            if (okhi) {
                int v0 = q8i((float)oacc[j][2] * c_av, inva5);
                int v1 = q8i((float)oacc[j][3] * c_av, inva5);
                *(unsigned short*)(g_ov + phi + n) =
                    (unsigned short)((v0 & 0xFF) | ((v1 & 0xFF) << 8));
            }
        }
    }
}

// ------------------------------ int8 IMMA GEMM (cp.async, 4-stage, 64B K) ---
// Dims: M,N multiples of 128; K multiple of 64 elems -> no bounds checks.
// 4 stages x (A 128x80B + B 128x80B) = 81920 bytes; wait_group 2.
#define GEMM_SMEM 81920

template <typename Epi>
__global__ void __launch_bounds__(256)
gemm_i8(int aid, int bid, int Kints, Epi epi) {
    extern __shared__ int gsm[];
    const int8_t* Ab = srcA(aid);
    const int8_t* Bb = srcB(bid);
    int bm = blockIdx.y * 128, bn = blockIdx.x * 128;
    int tid = threadIdx.x;
    int lane = tid & 31, wid = tid >> 5;
    int wm = wid >> 2, wn = wid & 3;
    int lrow = lane >> 2, lk = lane & 3;
    int srow = tid >> 2;          // 0..63
    int slot = tid & 3;

    uint32_t sbase = (uint32_t)__cvta_generic_to_shared(gsm);
    const int* Abase = (const int*)Ab + (size_t)(bm + srow) * Kints + slot * 4;
    const int* Bbase = (const int*)Bb + (size_t)(bn + srow) * Kints + slot * 4;
    size_t rowskip = (size_t)64 * Kints;
    uint32_t a_off = sbase + srow * 80 + slot * 16;
    uint32_t b_off = sbase + 40960 + srow * 80 + slot * 16;

    int acc[4][4][4];
#pragma unroll
    for (int i = 0; i < 4; ++i)
#pragma unroll
        for (int j = 0; j < 4; ++j)
#pragma unroll
            for (int r = 0; r < 4; ++r) acc[i][j][r] = 0;

    auto load_tile = [&](int kt, int stg) {
        int k0 = kt * 16;
        const int* ga = Abase + k0;
        const int* gb = Bbase + k0;
        uint32_t ao = a_off + stg * 10240;
        uint32_t bo = b_off + stg * 10240;
        CP_ASYNC16(ao, ga);
        CP_ASYNC16(ao + 64 * 80, ga + rowskip);
        CP_ASYNC16(bo, gb);
        CP_ASYNC16(bo + 64 * 80, gb + rowskip);
        CP_COMMIT();
    };

    int nk = Kints >> 4;
    load_tile(0, 0);
    load_tile(1, 1);
    load_tile(2, 2);

    for (int kt = 0; kt < nk; ++kt) {
        CP_WAIT2();
        __syncthreads();
        int cur = kt & 3;
        const int* sAc = gsm + cur * 2560;
        const int* sBc = gsm + 10240 + cur * 2560;
#pragma unroll
        for (int kc = 0; kc < 2; ++kc) {
            int kb = kc * 8;
            int b0[4], b1[4];
#pragma unroll
            for (int j = 0; j < 4; ++j) {
                int col = wn * 32 + j * 8 + lrow;
                b0[j] = sBc[col * 20 + kb + lk];
                b1[j] = sBc[col * 20 + kb + 4 + lk];
            }
#pragma unroll
            for (int i = 0; i < 4; ++i) {
                int r0 = wm * 64 + i * 16 + lrow;
                int a0 = sAc[r0 * 20 + kb + lk];
                int a1 = sAc[(r0 + 8) * 20 + kb + lk];
                int a2 = sAc[r0 * 20 + kb + 4 + lk];
                int a3 = sAc[(r0 + 8) * 20 + kb + 4 + lk];
#pragma unroll
                for (int j = 0; j < 4; ++j)
                    mma_s8(acc[i][j][0], acc[i][j][1], acc[i][j][2], acc[i][j][3],
                           a0, a1, a2, a3, b0[j], b1[j]);
            }
        }
        if (kt + 3 < nk) load_tile(kt + 3, (kt + 3) & 3);
    }

    epi.prep();
#pragma unroll
    for (int i = 0; i < 4; ++i) {
        int m0 = bm + wm * 64 + i * 16 + lrow;
#pragma unroll
        for (int j = 0; j < 4; ++j) {
            int n0 = bn + wn * 32 + j * 8 + lk * 2;
            epi(acc[i][j][0], m0, n0);
            epi(acc[i][j][1], m0, n0 + 1);
            epi(acc[i][j][2], m0 + 8, n0);
            epi(acc[i][j][3], m0 + 8, n0 + 1);
        }
    }
}

// ------------------------------ GEMM epilogues ------------------------------
struct EpiQKV {
    const float* as; const float* ws; const float* qb;
    float s1, inv0, inv1, inv2;
    __device__ void prep() {
        s1 = as[4] * ws[0];
        inv0 = 1.0f / as[0]; inv1 = 1.0f / as[1]; inv2 = 1.0f / as[2];
    }
    __device__ void operator()(int acc, int m, int n) const {
        float f = (float)acc * s1 + qb[n];
        int qi = (n >= 1536) ? 2 : (n >= 768 ? 1 : 0);
        int rem = n - qi * 768;
        int head = rem >> 6, d = rem & 63;
        int b = m >> 12, r = (m >> 6) & 63, c = m & 63;
        int wr = r / WSZ, lr = r - wr * WSZ;
        int wc = c / WSZ, lc = c - wc * WSZ;
        int wi = b * 25 + wr * 5 + wc;
        int t = lr * WSZ + lc;
        int bh = wi * NHEAD + head;
        if (qi == 0)      g_q [((size_t)bh * NTOK + t) * HDIM + d] = fq8m(f, inv0);
        else if (qi == 1) g_k [((size_t)bh * NTOK + t) * HDIM + d] = fq8m(f, inv1);
        else              g_vT[((size_t)bh * HDIM + d) * VPAD + t] = fq8m(f, inv2);
    }
};
struct EpiProj {
    const float* as; const float* ws; const float* pb; const float* x;
    float s1;
    __device__ void prep() { s1 = as[5] * ws[1]; }
    __device__ void operator()(int acc, int m, int n) const {
        size_t idx = (size_t)m * DIMC + n;
        g_xres[idx] = x[idx] + (float)acc * s1 + pb[n];
    }
};
struct EpiL1 {
    const float* as; const float* ws; const float* lb;
    float s1, inv7;
    __device__ void prep() { s1 = as[6] * ws[2]; inv7 = 1.0f / as[7]; }
    __device__ void operator()(int acc, int m, int n) const {
        float f = (float)acc * s1 + lb[n];
        float xx = f * 0.70710678118654752f;
        float ax = fabsf(xx);
        float t = __fdividef(1.0f, 1.0f + 0.3275911f * ax);
        float poly = t * (0.254829592f + t * (-0.284496736f + t * (1.421413741f +
                     t * (-1.453152027f + t * 1.061405429f))));
        float erfv = 1.0f - poly * __expf(-xx * xx);
        erfv = copysignf(erfv, xx);
        float g = 0.5f * f * (1.0f + erfv);
        g_hbuf[(size_t)m * MLPD + n] = fq8m(g, inv7);
    }
};
struct EpiL2 {
    const float* as; const float* ws; const float* lb; float* out;
    float s1;
    __device__ void prep() { s1 = as[7] * ws[3]; }
    __device__ void operator()(int acc, int m, int n) const {
        size_t idx = (size_t)m * DIMC + n;
        out[idx] = g_xres[idx] + (float)acc * s1 + lb[n];
    }
};

// ------------------------------ launch --------------------------------------
extern "C" void kernel_launch(void* const* d_in, const int* in_sizes, int n_in,
                              void* d_out, int out_size) {
    const float* x      = (const float*)d_in[0];
    const float* ln1_w  = (const float*)d_in[1];
    const float* ln1_b  = (const float*)d_in[2];
    const float* ln2_w  = (const float*)d_in[3];
    const float* ln2_b  = (const float*)d_in[4];
    const float* qkv_w  = (const float*)d_in[5];
    const float* qkv_b  = (const float*)d_in[6];
    const float* proj_w = (const float*)d_in[7];
    const float* proj_b = (const float*)d_in[8];
    const float* lin1_w = (const float*)d_in[9];
    const float* lin1_b = (const float*)d_in[10];
    const float* lin2_w = (const float*)d_in[11];
    const float* lin2_b = (const float*)d_in[12];
    const float* rph    = (const float*)d_in[13];
    const float* rpw    = (const float*)d_in[14];
    const float* asc    = (const float*)d_in[15];
    const float* wsc    = (const float*)d_in[16];
    float* out = (float*)d_out;

    cudaFuncSetAttribute(attn_fused_kernel, cudaFuncAttributeMaxDynamicSharedMemorySize, ATT_SMEM);
    cudaFuncSetAttribute(gemm_i8<EpiQKV>,  cudaFuncAttributeMaxDynamicSharedMemorySize, GEMM_SMEM);
    cudaFuncSetAttribute(gemm_i8<EpiProj>, cudaFuncAttributeMaxDynamicSharedMemorySize, GEMM_SMEM);
    cudaFuncSetAttribute(gemm_i8<EpiL1>,   cudaFuncAttributeMaxDynamicSharedMemorySize, GEMM_SMEM);
    cudaFuncSetAttribute(gemm_i8<EpiL2>,   cudaFuncAttributeMaxDynamicSharedMemorySize, GEMM_SMEM);

    quant_w_all<<<(QW_TOT + 255) / 256, 256>>>(qkv_w, proj_w, lin1_w, lin2_w, wsc);

    ln1_kernel<<<PIX / 8, 256>>>(x, ln1_w, ln1_b, asc);
    pad_qkv_kernel<<<NWIN, 256>>>(qkv_b, asc);

    gemm_i8<EpiQKV><<<dim3(18, 128), 256, GEMM_SMEM>>>(0, 0, DIMC / 4,
                                                       EpiQKV{asc, wsc, qkv_b});

    relpos_kernel<<<BHD, 224>>>(rph, rpw, asc);
    attn_fused_kernel<<<BHD, 416, ATT_SMEM>>>(asc);

    gemm_i8<EpiProj><<<dim3(6, 128), 256, GEMM_SMEM>>>(3, 3, DIMC / 4,
                                                       EpiProj{asc, wsc, proj_b, x});

    ln2_kernel<<<PIX / 8, 256>>>(ln2_w, ln2_b, asc);

    gemm_i8<EpiL1><<<dim3(24, 128), 256, GEMM_SMEM>>>(4, 4, DIMC / 4,
                                                      EpiL1{asc, wsc, lin1_b});
    gemm_i8<EpiL2><<<dim3(6, 128), 256, GEMM_SMEM>>>(5, 5, MLPD / 4,
                                                     EpiL2{asc, wsc, lin2_b, out});
}

// round 13
// speedup vs baseline: 1.0616x; 1.0066x over previous
#include <cuda_runtime.h>
#include <stdint.h>
#include <math.h>

// ---------------------------------------------------------------------------
// QunatEncoderBlock: windowed attention + MLP with 8-bit fake quantization.
// Matmuls exact in int8->int32 via mma.sync m16n8k32 (legacy tensor-pipe path
// on sm_103a, ~87% achievable; tcgen05 blocked by compute_103 PTX target).
// Round 13: rel-pos bias fused INTO attention (relpos kernel + g_relh/g_relw
// eliminated); GEMM reverted to measured-best round-10 body (3-stage, wait 1).
// ---------------------------------------------------------------------------

#define DIMC   768
#define NHEAD  12
#define HDIM   64
#define MLPD   3072
#define WSZ    14
#define NTOK   196
#define NWIN   100
#define BHD    1200
#define PIX    16384
#define HH     64
#define WW     64
#define VPAD   208

// ------------------------------ scratch (device globals) -------------------
__device__ __align__(16) int8_t g_winq [PIX * DIMC];
__device__ __align__(16) int8_t g_wqkv [3 * DIMC * DIMC];
__device__ __align__(16) int8_t g_wproj[DIMC * DIMC];
__device__ __align__(16) int8_t g_wl1  [MLPD * DIMC];
__device__ __align__(16) int8_t g_wl2  [DIMC * MLPD];
__device__ __align__(16) int8_t g_q    [BHD * NTOK * HDIM];
__device__ __align__(16) int8_t g_k    [BHD * NTOK * HDIM];
__device__ __align__(16) int8_t g_vT   [BHD * HDIM * VPAD];
__device__ __align__(16) int8_t g_ov   [PIX * DIMC];
__device__ float  g_xres[(size_t)PIX * DIMC];
__device__ __align__(16) int8_t g_y    [PIX * DIMC];
__device__ __align__(16) int8_t g_hbuf [(size_t)PIX * MLPD];

__device__ __forceinline__ const int8_t* srcA(int id) {
    switch (id) { case 0: return g_winq; case 3: return g_ov;
                  case 4: return g_y;    default: return g_hbuf; }
}
__device__ __forceinline__ const int8_t* srcB(int id) {
    switch (id) { case 0: return g_wqkv; case 3: return g_wproj;
                  case 4: return g_wl1;  default: return g_wl2; }
}

// ------------------------------ helpers ------------------------------------
__device__ __forceinline__ int q8i(float x, float inv) {
    float r = rintf(x * inv);
    return (int)fminf(fmaxf(r, -128.0f), 127.0f);
}
__device__ __forceinline__ int8_t fq8m(float x, float inv) { return (int8_t)q8i(x, inv); }

__device__ __forceinline__ void mma_s8(int& c0, int& c1, int& c2, int& c3,
                                       int a0, int a1, int a2, int a3, int b0, int b1) {
    asm volatile(
        "mma.sync.aligned.m16n8k32.row.col.s32.s8.s8.s32 "
        "{%0,%1,%2,%3}, {%4,%5,%6,%7}, {%8,%9}, {%0,%1,%2,%3};"
        : "+r"(c0), "+r"(c1), "+r"(c2), "+r"(c3)
        : "r"(a0), "r"(a1), "r"(a2), "r"(a3), "r"(b0), "r"(b1));
}

#define CP_ASYNC16(dst, src) \
    asm volatile("cp.async.cg.shared.global [%0], [%1], 16;" :: "r"(dst), "l"(src))
#define CP_COMMIT() asm volatile("cp.async.commit_group;" ::: "memory")
#define CP_WAIT1()  asm volatile("cp.async.wait_group 1;" ::: "memory")

// ------------------------------ fused weight quantization ------------------
#define QW_N0 442368
#define QW_N1 147456
#define QW_N2 589824
#define QW_TOT (QW_N0 + QW_N1 + QW_N2 + QW_N2)

__global__ void __launch_bounds__(256)
quant_w_all(const float* __restrict__ w0, const float* __restrict__ w1,
            const float* __restrict__ w2, const float* __restrict__ w3,
            const float* __restrict__ ws) {
    int i = blockIdx.x * blockDim.x + threadIdx.x;
    if (i >= QW_TOT) return;
    const float* src; int li; float inv; int8_t* dst;
    if (i < QW_N0)                      { src = w0; li = i;                         inv = 1.0f / ws[0]; dst = g_wqkv; }
    else if (i < QW_N0 + QW_N1)         { src = w1; li = i - QW_N0;                 inv = 1.0f / ws[1]; dst = g_wproj; }
    else if (i < QW_N0 + QW_N1 + QW_N2) { src = w2; li = i - QW_N0 - QW_N1;         inv = 1.0f / ws[2]; dst = g_wl1; }
    else                                { src = w3; li = i - QW_N0 - QW_N1 - QW_N2; inv = 1.0f / ws[3]; dst = g_wl2; }
    float4 v = ((const float4*)src)[li];
    int p = (q8i(v.x, inv) & 255) | ((q8i(v.y, inv) & 255) << 8) |
            ((q8i(v.z, inv) & 255) << 16) | ((q8i(v.w, inv) & 255) << 24);
    ((int*)dst)[li] = p;
}

// ------------------------------ LN kernels (warp per token) ----------------
__device__ __forceinline__ void ln_row(const float* __restrict__ xp,
                                       const float* __restrict__ lw,
                                       const float* __restrict__ lb,
                                       float isc, int8_t* __restrict__ outp,
                                       int lane) {
    const float4* xp4 = (const float4*)xp;
    float4 v[6];
    float s = 0.f;
#pragma unroll
    for (int j = 0; j < 6; ++j) {
        v[j] = xp4[lane + 32 * j];
        s += v[j].x + v[j].y + v[j].z + v[j].w;
    }
#pragma unroll
    for (int o = 16; o > 0; o >>= 1) s += __shfl_xor_sync(~0u, s, o);
    float mu = s * (1.0f / DIMC);
    float sq = 0.f;
#pragma unroll
    for (int j = 0; j < 6; ++j) {
        float a = v[j].x - mu, b = v[j].y - mu, c = v[j].z - mu, d = v[j].w - mu;
        sq += a * a + b * b + c * c + d * d;
    }
#pragma unroll
    for (int o = 16; o > 0; o >>= 1) sq += __shfl_xor_sync(~0u, sq, o);
    float inv = 1.0f / sqrtf(sq * (1.0f / DIMC) + 1e-6f);
    const float4* lw4 = (const float4*)lw;
    const float4* lb4 = (const float4*)lb;
#pragma unroll
    for (int j = 0; j < 6; ++j) {
        float4 w4 = lw4[lane + 32 * j];
        float4 b4 = lb4[lane + 32 * j];
        int p = (q8i((v[j].x - mu) * inv * w4.x + b4.x, isc) & 255)
              | ((q8i((v[j].y - mu) * inv * w4.y + b4.y, isc) & 255) << 8)
              | ((q8i((v[j].z - mu) * inv * w4.z + b4.z, isc) & 255) << 16)
              | ((q8i((v[j].w - mu) * inv * w4.w + b4.w, isc) & 255) << 24);
        ((int*)outp)[lane + 32 * j] = p;
    }
}

__global__ void __launch_bounds__(256)
ln1_kernel(const float* __restrict__ x, const float* __restrict__ lw,
           const float* __restrict__ lb, const float* __restrict__ as) {
    int lane = threadIdx.x & 31, wid = threadIdx.x >> 5;
    int m = blockIdx.x * 8 + wid;
    ln_row(x + (size_t)m * DIMC, lw, lb, 1.0f / as[4], g_winq + (size_t)m * DIMC, lane);
}

__global__ void __launch_bounds__(256)
ln2_kernel(const float* __restrict__ lw, const float* __restrict__ lb,
           const float* __restrict__ as) {
    int lane = threadIdx.x & 31, wid = threadIdx.x >> 5;
    int m = blockIdx.x * 8 + wid;
    ln_row(g_xres + (size_t)m * DIMC, lw, lb, 1.0f / as[6], g_y + (size_t)m * DIMC, lane);
}

// ------------------------------ pad-token q/k/vT fill ----------------------
__global__ void __launch_bounds__(256)
pad_qkv_kernel(const float* __restrict__ qb, const float* __restrict__ as) {
    int wi = blockIdx.x;
    int rem = wi % 25, wr = rem / 5, wc = rem % 5;
    if (wr < 4 && wc < 4) return;
    __shared__ int sq[192], sk[192];
    __shared__ int8_t sv[768];
    int tid = threadIdx.x;
    float inv0 = 1.0f / as[0], inv1 = 1.0f / as[1], inv2 = 1.0f / as[2];
    for (int i = tid; i < 192; i += 256) {
        int n = i * 4;
        sq[i] = (q8i(qb[n], inv0) & 255) | ((q8i(qb[n+1], inv0) & 255) << 8)
              | ((q8i(qb[n+2], inv0) & 255) << 16) | ((q8i(qb[n+3], inv0) & 255) << 24);
        sk[i] = (q8i(qb[768+n], inv1) & 255) | ((q8i(qb[768+n+1], inv1) & 255) << 8)
              | ((q8i(qb[768+n+2], inv1) & 255) << 16) | ((q8i(qb[768+n+3], inv1) & 255) << 24);
    }
    for (int i = tid; i < 768; i += 256) sv[i] = fq8m(qb[1536 + i], inv2);
    __syncthreads();
    int lane = tid & 31, w = tid >> 5;
    for (int t = w; t < NTOK; t += 8) {
        int lr = t / WSZ, lc = t % WSZ;
        bool pad = (wr == 4 && lr >= 8) || (wc == 4 && lc >= 8);
        if (!pad) continue;
        for (int i = lane; i < 192; i += 32) {
            int head = i >> 4, di = i & 15;
            ((int*)(g_q + ((size_t)(wi * NHEAD + head) * NTOK + t) * HDIM))[di] = sq[i];
            ((int*)(g_k + ((size_t)(wi * NHEAD + head) * NTOK + t) * HDIM))[di] = sk[i];
        }
        for (int i = lane; i < 768; i += 32) {
            int head = i >> 6, d = i & 63;
            g_vT[((size_t)(wi * NHEAD + head) * HDIM + d) * VPAD + t] = sv[i];
        }
    }
}

// ------------------------------ fused attention (+rel-pos bias) -------------
// 416 threads = 13 warps; each warp owns one 16-row strip.
// Rel-pos bias computed in-kernel into smem (sRel) -- no global rel arrays.
#define QSTR  20
#define SSTR  60
#define SQ_OFF   0
#define SK_OFF   (208 * QSTR)                  // 4160
#define SV_OFF   (SK_OFF + 200 * QSTR)         // 8160
#define SS_OFF   (SV_OFF + 64 * SSTR)          // 12000
#define RH_OFF   (SS_OFF + 208 * SSTR)         // 24480
#define RW_OFF   (RH_OFF + 64 * 28)            // 26272
#define REL_OFF  (RW_OFF + 64 * 28)            // 28064
#define ATT_SMEM ((REL_OFF + 208 * 28) * 4)    // 135552 bytes

__global__ void __launch_bounds__(416)
attn_fused_kernel(const float* __restrict__ rph, const float* __restrict__ rpw,
                  const float* __restrict__ as) {
    extern __shared__ int sm[];
    int* sQ = sm + SQ_OFF; int* sK = sm + SK_OFF;
    int* sVT = sm + SV_OFF; int* sS = sm + SS_OFF;
    float* sRhT = (float*)(sm + RH_OFF);
    float* sRwT = (float*)(sm + RW_OFF);
    float* sRel = (float*)(sm + REL_OFF);
    int bh = blockIdx.x, tid = threadIdx.x;
    int lane = tid & 31, wid = tid >> 5;
    int lrow = lane >> 2, lk = lane & 3;

    const int8_t* qg = g_q  + (size_t)bh * NTOK * HDIM;
    const int8_t* kg = g_k  + (size_t)bh * NTOK * HDIM;
    const int8_t* vg = g_vT + (size_t)bh * HDIM * VPAD;
    for (int idx = tid; idx < 208 * 4; idx += 416) {
        int row = idx >> 2, slot = idx & 3;
        int4 v = make_int4(0, 0, 0, 0);
        if (row < NTOK) v = *(const int4*)(qg + row * HDIM + slot * 16);
        *(int4*)&sQ[row * QSTR + slot * 4] = v;
    }
    for (int idx = tid; idx < 200 * 4; idx += 416) {
        int row = idx >> 2, slot = idx & 3;
        int4 v = make_int4(0, 0, 0, 0);
        if (row < NTOK) v = *(const int4*)(kg + row * HDIM + slot * 16);
        *(int4*)&sK[row * QSTR + slot * 4] = v;
    }
    for (int idx = tid; idx < 64 * 13; idx += 416) {
        int row = idx / 13, slot = idx % 13;
        *(int4*)&sVT[row * SSTR + slot * 4] = *(const int4*)(vg + row * VPAD + slot * 16);
    }
    for (int idx = tid; idx < 208 * 6; idx += 416)
        sS[(idx / 6) * SSTR + 50 + (idx % 6)] = 0;
    // stage transposed rel-pos tables: [c][r], stride 28
    for (int i = tid; i < 27 * 64; i += 416) {
        int r = i >> 6, c = i & 63;
        sRhT[c * 28 + r] = rph[i];
        sRwT[c * 28 + r] = rpw[i];
    }
    __syncthreads();

    float a0s = as[0];
    // ---- in-kernel rel-pos bias: thread t handles row t (t < 196) ----------
    if (tid < NTOK) {
        int t = tid;
        int hh = t / WSZ, ww2 = t % WSZ;
        float ah[WSZ], aw[WSZ];
#pragma unroll
        for (int kk = 0; kk < WSZ; ++kk) { ah[kk] = 0.f; aw[kk] = 0.f; }
#pragma unroll
        for (int j = 0; j < 16; ++j) {
            int packed = sQ[t * QSTR + j];
#pragma unroll
            for (int b = 0; b < 4; ++b) {
                int c = j * 4 + b;
                float qv = (float)((packed << (24 - 8 * b)) >> 24);
                const float* ph = &sRhT[c * 28 + hh + 13];
                const float* pw = &sRwT[c * 28 + ww2 + 13];
#pragma unroll
                for (int kk = 0; kk < WSZ; ++kk) {
                    ah[kk] += qv * ph[-kk];
                    aw[kk] += qv * pw[-kk];
                }
            }
        }
#pragma unroll
        for (int kk = 0; kk < WSZ; ++kk) {
            sRel[t * 28 + kk]      = ah[kk] * a0s;
            sRel[t * 28 + 14 + kk] = aw[kk] * a0s;
        }
    }
    __syncthreads();

    float c_qk = 0.125f * a0s * as[1];
    float inva3 = 1.0f / as[3];
    float c_av = as[3] * as[2];
    float inva5 = 1.0f / as[5];
    int wi = bh / NHEAD, head = bh % NHEAD;
    int wrem = wi % 25, wb = wi / 25, wwr = wrem / 5, wwc = wrem % 5;
    char* sSb = (char*)sS;

    {
        int s = wid;
        int m_lo = s * 16 + lrow, m_hi = m_lo + 8;
        int acc[25][4];
#pragma unroll
        for (int t = 0; t < 25; ++t) { acc[t][0]=acc[t][1]=acc[t][2]=acc[t][3]=0; }
#pragma unroll
        for (int kc = 0; kc < 2; ++kc) {
            int kb = kc * 8;
            int a0 = sQ[m_lo * QSTR + kb + lk];
            int a1 = sQ[m_hi * QSTR + kb + lk];
            int a2 = sQ[m_lo * QSTR + kb + 4 + lk];
            int a3 = sQ[m_hi * QSTR + kb + 4 + lk];
#pragma unroll
            for (int t = 0; t < 25; ++t) {
                int col = t * 8 + lrow;
                mma_s8(acc[t][0], acc[t][1], acc[t][2], acc[t][3],
                       a0, a1, a2, a3, sK[col * QSTR + kb + lk], sK[col * QSTR + kb + 4 + lk]);
            }
        }
        bool vlo = (m_lo < NTOK), vhi = (m_hi < NTOK);
        const float* rlo_p = &sRel[m_lo * 28];
        const float* rhi_p = &sRel[m_hi * 28];
#pragma unroll
        for (int t = 0; t < 25; ++t) {
#pragma unroll
            for (int r = 0; r < 4; ++r) {
                int n = t * 8 + lk * 2 + (r & 1);
                bool vm = (r < 2) ? vlo : vhi;
                float f;
                if (n < NTOK && vm) {
                    const float* rp = (r < 2) ? rlo_p : rhi_p;
                    f = (float)acc[t][r] * c_qk + rp[n / WSZ] + rp[14 + n % WSZ];
                } else f = -1e30f;
                acc[t][r] = __float_as_int(f);
            }
        }
        float mx0 = -1e30f, mx1 = -1e30f;
#pragma unroll
        for (int t = 0; t < 25; ++t) {
            mx0 = fmaxf(mx0, fmaxf(__int_as_float(acc[t][0]), __int_as_float(acc[t][1])));
            mx1 = fmaxf(mx1, fmaxf(__int_as_float(acc[t][2]), __int_as_float(acc[t][3])));
        }
        mx0 = fmaxf(mx0, __shfl_xor_sync(~0u, mx0, 1)); mx0 = fmaxf(mx0, __shfl_xor_sync(~0u, mx0, 2));
        mx1 = fmaxf(mx1, __shfl_xor_sync(~0u, mx1, 1)); mx1 = fmaxf(mx1, __shfl_xor_sync(~0u, mx1, 2));
        float s0 = 0.f, s1 = 0.f;
#pragma unroll
        for (int t = 0; t < 25; ++t) {
            float e0 = __expf(__int_as_float(acc[t][0]) - mx0);
            float e1 = __expf(__int_as_float(acc[t][1]) - mx0);
            float e2 = __expf(__int_as_float(acc[t][2]) - mx1);
            float e3 = __expf(__int_as_float(acc[t][3]) - mx1);
            acc[t][0] = __float_as_int(e0); acc[t][1] = __float_as_int(e1);
            acc[t][2] = __float_as_int(e2); acc[t][3] = __float_as_int(e3);
            s0 += e0 + e1; s1 += e2 + e3;
        }
        s0 += __shfl_xor_sync(~0u, s0, 1); s0 += __shfl_xor_sync(~0u, s0, 2);
        s1 += __shfl_xor_sync(~0u, s1, 1); s1 += __shfl_xor_sync(~0u, s1, 2);
        float r0 = inva3 / s0, r1 = inva3 / s1;
#pragma unroll
        for (int t = 0; t < 25; ++t) {
            int v00 = q8i(__int_as_float(acc[t][0]), r0);
            int v01 = q8i(__int_as_float(acc[t][1]), r0);
            int v10 = q8i(__int_as_float(acc[t][2]), r1);
            int v11 = q8i(__int_as_float(acc[t][3]), r1);
            *(unsigned short*)(sSb + m_lo * (SSTR * 4) + t * 8 + lk * 2) =
                (unsigned short)((v00 & 0xFF) | ((v01 & 0xFF) << 8));
            *(unsigned short*)(sSb + m_hi * (SSTR * 4) + t * 8 + lk * 2) =
                (unsigned short)((v10 & 0xFF) | ((v11 & 0xFF) << 8));
        }
        __syncwarp();
        int oacc[8][4];
#pragma unroll
        for (int j = 0; j < 8; ++j) { oacc[j][0]=oacc[j][1]=oacc[j][2]=oacc[j][3]=0; }
#pragma unroll
        for (int kc = 0; kc < 7; ++kc) {
            int kb = kc * 8;
            int a0 = sS[m_lo * SSTR + kb + lk];
            int a1 = sS[m_hi * SSTR + kb + lk];
            int a2 = sS[m_lo * SSTR + kb + 4 + lk];
            int a3 = sS[m_hi * SSTR + kb + 4 + lk];
#pragma unroll
            for (int j = 0; j < 8; ++j) {
                int col = j * 8 + lrow;
                mma_s8(oacc[j][0], oacc[j][1], oacc[j][2], oacc[j][3],
                       a0, a1, a2, a3, sVT[col * SSTR + kb + lk], sVT[col * SSTR + kb + 4 + lk]);
            }
        }
        int rlo = wwr * WSZ + m_lo / WSZ, clo = wwc * WSZ + m_lo % WSZ;
        int rhi = wwr * WSZ + m_hi / WSZ, chi = wwc * WSZ + m_hi % WSZ;
        bool oklo = vlo && rlo < HH && clo < WW;
        bool okhi = vhi && rhi < HH && chi < WW;
        size_t plo = (((size_t)(wb * HH + rlo)) * WW + clo) * DIMC + head * HDIM;
        size_t phi = (((size_t)(wb * HH + rhi)) * WW + chi) * DIMC + head * HDIM;
#pragma unroll
        for (int j = 0; j < 8; ++j) {
            int n = j * 8 + lk * 2;
            if (oklo) {
                int v0 = q8i((float)oacc[j][0] * c_av, inva5);
                int v1 = q8i((float)oacc[j][1] * c_av, inva5);
                *(unsigned short*)(g_ov + plo + n) =
                    (unsigned short)((v0 & 0xFF) | ((v1 & 0xFF) << 8));
            }
            if (okhi) {
                int v0 = q8i((float)oacc[j][2] * c_av, inva5);
                int v1 = q8i((float)oacc[j][3] * c_av, inva5);
                *(unsigned short*)(g_ov + phi + n) =
                    (unsigned short)((v0 & 0xFF) | ((v1 & 0xFF) << 8));
            }
        }
    }
}

// ------------------------------ int8 IMMA GEMM (cp.async, 3-stage, 64B K) ---
// Dims: M,N multiples of 128; K multiple of 64 elems -> no bounds checks.
// 3 stages x (A 128x80B + B 128x80B) = 61440 bytes; wait_group 1.
#define GEMM_SMEM 61440

template <typename Epi>
__global__ void __launch_bounds__(256)
gemm_i8(int aid, int bid, int Kints, Epi epi) {
    extern __shared__ int gsm[];
    const int8_t* Ab = srcA(aid);
    const int8_t* Bb = srcB(bid);
    int bm = blockIdx.y * 128, bn = blockIdx.x * 128;
    int tid = threadIdx.x;
    int lane = tid & 31, wid = tid >> 5;
    int wm = wid >> 2, wn = wid & 3;
    int lrow = lane >> 2, lk = lane & 3;
    int srow = tid >> 2;
    int slot = tid & 3;

    uint32_t sbase = (uint32_t)__cvta_generic_to_shared(gsm);
    const int* Abase = (const int*)Ab + (size_t)(bm + srow) * Kints + slot * 4;
    const int* Bbase = (const int*)Bb + (size_t)(bn + srow) * Kints + slot * 4;
    size_t rowskip = (size_t)64 * Kints;
    uint32_t a_off = sbase + srow * 80 + slot * 16;
    uint32_t b_off = sbase + 30720 + srow * 80 + slot * 16;

    int acc[4][4][4];
#pragma unroll
    for (int i = 0; i < 4; ++i)
#pragma unroll
        for (int j = 0; j < 4; ++j)
#pragma unroll
            for (int r = 0; r < 4; ++r) acc[i][j][r] = 0;

    auto load_tile = [&](int kt, int stg) {
        int k0 = kt * 16;
        const int* ga = Abase + k0;
        const int* gb = Bbase + k0;
        uint32_t ao = a_off + stg * 10240;
        uint32_t bo = b_off + stg * 10240;
        CP_ASYNC16(ao, ga);
        CP_ASYNC16(ao + 64 * 80, ga + rowskip);
        CP_ASYNC16(bo, gb);
        CP_ASYNC16(bo + 64 * 80, gb + rowskip);
        CP_COMMIT();
    };

    int nk = Kints >> 4;
    load_tile(0, 0);
    load_tile(1, 1);

    for (int kt = 0; kt < nk; ++kt) {
        CP_WAIT1();
        __syncthreads();
        int cur = kt - (kt / 3) * 3;
        const int* sAc = gsm + cur * 2560;
        const int* sBc = gsm + 7680 + cur * 2560;
#pragma unroll
        for (int kc = 0; kc < 2; ++kc) {
            int kb = kc * 8;
            int b0[4], b1[4];
#pragma unroll
            for (int j = 0; j < 4; ++j) {
                int col = wn * 32 + j * 8 + lrow;
                b0[j] = sBc[col * 20 + kb + lk];
                b1[j] = sBc[col * 20 + kb + 4 + lk];
            }
#pragma unroll
            for (int i = 0; i < 4; ++i) {
                int r0 = wm * 64 + i * 16 + lrow;
                int a0 = sAc[r0 * 20 + kb + lk];
                int a1 = sAc[(r0 + 8) * 20 + kb + lk];
                int a2 = sAc[r0 * 20 + kb + 4 + lk];
                int a3 = sAc[(r0 + 8) * 20 + kb + 4 + lk];
#pragma unroll
                for (int j = 0; j < 4; ++j)
                    mma_s8(acc[i][j][0], acc[i][j][1], acc[i][j][2], acc[i][j][3],
                           a0, a1, a2, a3, b0[j], b1[j]);
            }
        }
        if (kt + 2 < nk) {
            int stg = kt + 2;
            stg -= (stg / 3) * 3;
            load_tile(kt + 2, stg);
        }
    }

    epi.prep();
#pragma unroll
    for (int i = 0; i < 4; ++i) {
        int m0 = bm + wm * 64 + i * 16 + lrow;
#pragma unroll
        for (int j = 0; j < 4; ++j) {
            int n0 = bn + wn * 32 + j * 8 + lk * 2;
            epi(acc[i][j][0], m0, n0);
            epi(acc[i][j][1], m0, n0 + 1);
            epi(acc[i][j][2], m0 + 8, n0);
            epi(acc[i][j][3], m0 + 8, n0 + 1);
        }
    }
}

// ------------------------------ GEMM epilogues ------------------------------
struct EpiQKV {
    const float* as; const float* ws; const float* qb;
    float s1, inv0, inv1, inv2;
    __device__ void prep() {
        s1 = as[4] * ws[0];
        inv0 = 1.0f / as[0]; inv1 = 1.0f / as[1]; inv2 = 1.0f / as[2];
    }
    __device__ void operator()(int acc, int m, int n) const {
        float f = (float)acc * s1 + qb[n];
        int qi = (n >= 1536) ? 2 : (n >= 768 ? 1 : 0);
        int rem = n - qi * 768;
        int head = rem >> 6, d = rem & 63;
        int b = m >> 12, r = (m >> 6) & 63, c = m & 63;
        int wr = r / WSZ, lr = r - wr * WSZ;
        int wc = c / WSZ, lc = c - wc * WSZ;
        int wi = b * 25 + wr * 5 + wc;
        int t = lr * WSZ + lc;
        int bh = wi * NHEAD + head;
        if (qi == 0)      g_q [((size_t)bh * NTOK + t) * HDIM + d] = fq8m(f, inv0);
        else if (qi == 1) g_k [((size_t)bh * NTOK + t) * HDIM + d] = fq8m(f, inv1);
        else              g_vT[((size_t)bh * HDIM + d) * VPAD + t] = fq8m(f, inv2);
    }
};
struct EpiProj {
    const float* as; const float* ws; const float* pb; const float* x;
    float s1;
    __device__ void prep() { s1 = as[5] * ws[1]; }
    __device__ void operator()(int acc, int m, int n) const {
        size_t idx = (size_t)m * DIMC + n;
        g_xres[idx] = x[idx] + (float)acc * s1 + pb[n];
    }
};
struct EpiL1 {
    const float* as; const float* ws; const float* lb;
    float s1, inv7;
    __device__ void prep() { s1 = as[6] * ws[2]; inv7 = 1.0f / as[7]; }
    __device__ void operator()(int acc, int m, int n) const {
        float f = (float)acc * s1 + lb[n];
        float xx = f * 0.70710678118654752f;
        float ax = fabsf(xx);
        float t = __fdividef(1.0f, 1.0f + 0.3275911f * ax);
        float poly = t * (0.254829592f + t * (-0.284496736f + t * (1.421413741f +
                     t * (-1.453152027f + t * 1.061405429f))));
        float erfv = 1.0f - poly * __expf(-xx * xx);
        erfv = copysignf(erfv, xx);
        float g = 0.5f * f * (1.0f + erfv);
        g_hbuf[(size_t)m * MLPD + n] = fq8m(g, inv7);
    }
};
struct EpiL2 {
    const float* as; const float* ws; const float* lb; float* out;
    float s1;
    __device__ void prep() { s1 = as[7] * ws[3]; }
    __device__ void operator()(int acc, int m, int n) const {
        size_t idx = (size_t)m * DIMC + n;
        out[idx] = g_xres[idx] + (float)acc * s1 + lb[n];
    }
};

// ------------------------------ launch --------------------------------------
extern "C" void kernel_launch(void* const* d_in, const int* in_sizes, int n_in,
                              void* d_out, int out_size) {
    const float* x      = (const float*)d_in[0];
    const float* ln1_w  = (const float*)d_in[1];
    const float* ln1_b  = (const float*)d_in[2];
    const float* ln2_w  = (const float*)d_in[3];
    const float* ln2_b  = (const float*)d_in[4];
    const float* qkv_w  = (const float*)d_in[5];
    const float* qkv_b  = (const float*)d_in[6];
    const float* proj_w = (const float*)d_in[7];
    const float* proj_b = (const float*)d_in[8];
    const float* lin1_w = (const float*)d_in[9];
    const float* lin1_b = (const float*)d_in[10];
    const float* lin2_w = (const float*)d_in[11];
    const float* lin2_b = (const float*)d_in[12];
    const float* rph    = (const float*)d_in[13];
    const float* rpw    = (const float*)d_in[14];
    const float* asc    = (const float*)d_in[15];
    const float* wsc    = (const float*)d_in[16];
    float* out = (float*)d_out;

    cudaFuncSetAttribute(attn_fused_kernel, cudaFuncAttributeMaxDynamicSharedMemorySize, ATT_SMEM);
    cudaFuncSetAttribute(gemm_i8<EpiQKV>,  cudaFuncAttributeMaxDynamicSharedMemorySize, GEMM_SMEM);
    cudaFuncSetAttribute(gemm_i8<EpiProj>, cudaFuncAttributeMaxDynamicSharedMemorySize, GEMM_SMEM);
    cudaFuncSetAttribute(gemm_i8<EpiL1>,   cudaFuncAttributeMaxDynamicSharedMemorySize, GEMM_SMEM);
    cudaFuncSetAttribute(gemm_i8<EpiL2>,   cudaFuncAttributeMaxDynamicSharedMemorySize, GEMM_SMEM);

    quant_w_all<<<(QW_TOT + 255) / 256, 256>>>(qkv_w, proj_w, lin1_w, lin2_w, wsc);

    ln1_kernel<<<PIX / 8, 256>>>(x, ln1_w, ln1_b, asc);
    pad_qkv_kernel<<<NWIN, 256>>>(qkv_b, asc);

    gemm_i8<EpiQKV><<<dim3(18, 128), 256, GEMM_SMEM>>>(0, 0, DIMC / 4,
                                                       EpiQKV{asc, wsc, qkv_b});

    attn_fused_kernel<<<BHD, 416, ATT_SMEM>>>(rph, rpw, asc);

    gemm_i8<EpiProj><<<dim3(6, 128), 256, GEMM_SMEM>>>(3, 3, DIMC / 4,
                                                       EpiProj{asc, wsc, proj_b, x});

    ln2_kernel<<<PIX / 8, 256>>>(ln2_w, ln2_b, asc);

    gemm_i8<EpiL1><<<dim3(24, 128), 256, GEMM_SMEM>>>(4, 4, DIMC / 4,
                                                      EpiL1{asc, wsc, lin1_b});
    gemm_i8<EpiL2><<<dim3(6, 128), 256, GEMM_SMEM>>>(5, 5, MLPD / 4,
                                                     EpiL2{asc, wsc, lin2_b, out});
}

// round 14
// speedup vs baseline: 1.0708x; 1.0087x over previous
#include <cuda_runtime.h>
#include <stdint.h>
#include <math.h>

// ---------------------------------------------------------------------------
// QunatEncoderBlock: windowed attention + MLP with 8-bit fake quantization.
// Matmuls exact in int8->int32 via mma.sync m16n8k32 (legacy tensor-pipe path
// on sm_103a, ~87% achievable; tcgen05 blocked by compute_103 PTX target).
// Round 14: paired GEMM epilogues (2-wide stores: ushort q/k, float2 residual
// paths, packed hbuf). Mainloop/attention/LN unchanged from round 13.
// ---------------------------------------------------------------------------

#define DIMC   768
#define NHEAD  12
#define HDIM   64
#define MLPD   3072
#define WSZ    14
#define NTOK   196
#define NWIN   100
#define BHD    1200
#define PIX    16384
#define HH     64
#define WW     64
#define VPAD   208

// ------------------------------ scratch (device globals) -------------------
__device__ __align__(16) int8_t g_winq [PIX * DIMC];
__device__ __align__(16) int8_t g_wqkv [3 * DIMC * DIMC];
__device__ __align__(16) int8_t g_wproj[DIMC * DIMC];
__device__ __align__(16) int8_t g_wl1  [MLPD * DIMC];
__device__ __align__(16) int8_t g_wl2  [DIMC * MLPD];
__device__ __align__(16) int8_t g_q    [BHD * NTOK * HDIM];
__device__ __align__(16) int8_t g_k    [BHD * NTOK * HDIM];
__device__ __align__(16) int8_t g_vT   [BHD * HDIM * VPAD];
__device__ __align__(16) int8_t g_ov   [PIX * DIMC];
__device__ float  g_xres[(size_t)PIX * DIMC];
__device__ __align__(16) int8_t g_y    [PIX * DIMC];
__device__ __align__(16) int8_t g_hbuf [(size_t)PIX * MLPD];

__device__ __forceinline__ const int8_t* srcA(int id) {
    switch (id) { case 0: return g_winq; case 3: return g_ov;
                  case 4: return g_y;    default: return g_hbuf; }
}
__device__ __forceinline__ const int8_t* srcB(int id) {
    switch (id) { case 0: return g_wqkv; case 3: return g_wproj;
                  case 4: return g_wl1;  default: return g_wl2; }
}

// ------------------------------ helpers ------------------------------------
__device__ __forceinline__ int q8i(float x, float inv) {
    float r = rintf(x * inv);
    return (int)fminf(fmaxf(r, -128.0f), 127.0f);
}
__device__ __forceinline__ int8_t fq8m(float x, float inv) { return (int8_t)q8i(x, inv); }

__device__ __forceinline__ void mma_s8(int& c0, int& c1, int& c2, int& c3,
                                       int a0, int a1, int a2, int a3, int b0, int b1) {
    asm volatile(
        "mma.sync.aligned.m16n8k32.row.col.s32.s8.s8.s32 "
        "{%0,%1,%2,%3}, {%4,%5,%6,%7}, {%8,%9}, {%0,%1,%2,%3};"
        : "+r"(c0), "+r"(c1), "+r"(c2), "+r"(c3)
        : "r"(a0), "r"(a1), "r"(a2), "r"(a3), "r"(b0), "r"(b1));
}

#define CP_ASYNC16(dst, src) \
    asm volatile("cp.async.cg.shared.global [%0], [%1], 16;" :: "r"(dst), "l"(src))
#define CP_COMMIT() asm volatile("cp.async.commit_group;" ::: "memory")
#define CP_WAIT1()  asm volatile("cp.async.wait_group 1;" ::: "memory")

// ------------------------------ fused weight quantization ------------------
#define QW_N0 442368
#define QW_N1 147456
#define QW_N2 589824
#define QW_TOT (QW_N0 + QW_N1 + QW_N2 + QW_N2)

__global__ void __launch_bounds__(256)
quant_w_all(const float* __restrict__ w0, const float* __restrict__ w1,
            const float* __restrict__ w2, const float* __restrict__ w3,
            const float* __restrict__ ws) {
    int i = blockIdx.x * blockDim.x + threadIdx.x;
    if (i >= QW_TOT) return;
    const float* src; int li; float inv; int8_t* dst;
    if (i < QW_N0)                      { src = w0; li = i;                         inv = 1.0f / ws[0]; dst = g_wqkv; }
    else if (i < QW_N0 + QW_N1)         { src = w1; li = i - QW_N0;                 inv = 1.0f / ws[1]; dst = g_wproj; }
    else if (i < QW_N0 + QW_N1 + QW_N2) { src = w2; li = i - QW_N0 - QW_N1;         inv = 1.0f / ws[2]; dst = g_wl1; }
    else                                { src = w3; li = i - QW_N0 - QW_N1 - QW_N2; inv = 1.0f / ws[3]; dst = g_wl2; }
    float4 v = ((const float4*)src)[li];
    int p = (q8i(v.x, inv) & 255) | ((q8i(v.y, inv) & 255) << 8) |
            ((q8i(v.z, inv) & 255) << 16) | ((q8i(v.w, inv) & 255) << 24);
    ((int*)dst)[li] = p;
}

// ------------------------------ LN kernels (warp per token) ----------------
__device__ __forceinline__ void ln_row(const float* __restrict__ xp,
                                       const float* __restrict__ lw,
                                       const float* __restrict__ lb,
                                       float isc, int8_t* __restrict__ outp,
                                       int lane) {
    const float4* xp4 = (const float4*)xp;
    float4 v[6];
    float s = 0.f;
#pragma unroll
    for (int j = 0; j < 6; ++j) {
        v[j] = xp4[lane + 32 * j];
        s += v[j].x + v[j].y + v[j].z + v[j].w;
    }
#pragma unroll
    for (int o = 16; o > 0; o >>= 1) s += __shfl_xor_sync(~0u, s, o);
    float mu = s * (1.0f / DIMC);
    float sq = 0.f;
#pragma unroll
    for (int j = 0; j < 6; ++j) {
        float a = v[j].x - mu, b = v[j].y - mu, c = v[j].z - mu, d = v[j].w - mu;
        sq += a * a + b * b + c * c + d * d;
    }
#pragma unroll
    for (int o = 16; o > 0; o >>= 1) sq += __shfl_xor_sync(~0u, sq, o);
    float inv = 1.0f / sqrtf(sq * (1.0f / DIMC) + 1e-6f);
    const float4* lw4 = (const float4*)lw;
    const float4* lb4 = (const float4*)lb;
#pragma unroll
    for (int j = 0; j < 6; ++j) {
        float4 w4 = lw4[lane + 32 * j];
        float4 b4 = lb4[lane + 32 * j];
        int p = (q8i((v[j].x - mu) * inv * w4.x + b4.x, isc) & 255)
              | ((q8i((v[j].y - mu) * inv * w4.y + b4.y, isc) & 255) << 8)
              | ((q8i((v[j].z - mu) * inv * w4.z + b4.z, isc) & 255) << 16)
              | ((q8i((v[j].w - mu) * inv * w4.w + b4.w, isc) & 255) << 24);
        ((int*)outp)[lane + 32 * j] = p;
    }
}

__global__ void __launch_bounds__(256)
ln1_kernel(const float* __restrict__ x, const float* __restrict__ lw,
           const float* __restrict__ lb, const float* __restrict__ as) {
    int lane = threadIdx.x & 31, wid = threadIdx.x >> 5;
    int m = blockIdx.x * 8 + wid;
    ln_row(x + (size_t)m * DIMC, lw, lb, 1.0f / as[4], g_winq + (size_t)m * DIMC, lane);
}

__global__ void __launch_bounds__(256)
ln2_kernel(const float* __restrict__ lw, const float* __restrict__ lb,
           const float* __restrict__ as) {
    int lane = threadIdx.x & 31, wid = threadIdx.x >> 5;
    int m = blockIdx.x * 8 + wid;
    ln_row(g_xres + (size_t)m * DIMC, lw, lb, 1.0f / as[6], g_y + (size_t)m * DIMC, lane);
}

// ------------------------------ pad-token q/k/vT fill ----------------------
__global__ void __launch_bounds__(256)
pad_qkv_kernel(const float* __restrict__ qb, const float* __restrict__ as) {
    int wi = blockIdx.x;
    int rem = wi % 25, wr = rem / 5, wc = rem % 5;
    if (wr < 4 && wc < 4) return;
    __shared__ int sq[192], sk[192];
    __shared__ int8_t sv[768];
    int tid = threadIdx.x;
    float inv0 = 1.0f / as[0], inv1 = 1.0f / as[1], inv2 = 1.0f / as[2];
    for (int i = tid; i < 192; i += 256) {
        int n = i * 4;
        sq[i] = (q8i(qb[n], inv0) & 255) | ((q8i(qb[n+1], inv0) & 255) << 8)
              | ((q8i(qb[n+2], inv0) & 255) << 16) | ((q8i(qb[n+3], inv0) & 255) << 24);
        sk[i] = (q8i(qb[768+n], inv1) & 255) | ((q8i(qb[768+n+1], inv1) & 255) << 8)
              | ((q8i(qb[768+n+2], inv1) & 255) << 16) | ((q8i(qb[768+n+3], inv1) & 255) << 24);
    }
    for (int i = tid; i < 768; i += 256) sv[i] = fq8m(qb[1536 + i], inv2);
    __syncthreads();
    int lane = tid & 31, w = tid >> 5;
    for (int t = w; t < NTOK; t += 8) {
        int lr = t / WSZ, lc = t % WSZ;
        bool pad = (wr == 4 && lr >= 8) || (wc == 4 && lc >= 8);
        if (!pad) continue;
        for (int i = lane; i < 192; i += 32) {
            int head = i >> 4, di = i & 15;
            ((int*)(g_q + ((size_t)(wi * NHEAD + head) * NTOK + t) * HDIM))[di] = sq[i];
            ((int*)(g_k + ((size_t)(wi * NHEAD + head) * NTOK + t) * HDIM))[di] = sk[i];
        }
        for (int i = lane; i < 768; i += 32) {
            int head = i >> 6, d = i & 63;
            g_vT[((size_t)(wi * NHEAD + head) * HDIM + d) * VPAD + t] = sv[i];
        }
    }
}

// ------------------------------ fused attention (+rel-pos bias) -------------
#define QSTR  20
#define SSTR  60
#define SQ_OFF   0
#define SK_OFF   (208 * QSTR)
#define SV_OFF   (SK_OFF + 200 * QSTR)
#define SS_OFF   (SV_OFF + 64 * SSTR)
#define RH_OFF   (SS_OFF + 208 * SSTR)
#define RW_OFF   (RH_OFF + 64 * 28)
#define REL_OFF  (RW_OFF + 64 * 28)
#define ATT_SMEM ((REL_OFF + 208 * 28) * 4)

__global__ void __launch_bounds__(416)
attn_fused_kernel(const float* __restrict__ rph, const float* __restrict__ rpw,
                  const float* __restrict__ as) {
    extern __shared__ int sm[];
    int* sQ = sm + SQ_OFF; int* sK = sm + SK_OFF;
    int* sVT = sm + SV_OFF; int* sS = sm + SS_OFF;
    float* sRhT = (float*)(sm + RH_OFF);
    float* sRwT = (float*)(sm + RW_OFF);
    float* sRel = (float*)(sm + REL_OFF);
    int bh = blockIdx.x, tid = threadIdx.x;
    int lane = tid & 31, wid = tid >> 5;
    int lrow = lane >> 2, lk = lane & 3;

    const int8_t* qg = g_q  + (size_t)bh * NTOK * HDIM;
    const int8_t* kg = g_k  + (size_t)bh * NTOK * HDIM;
    const int8_t* vg = g_vT + (size_t)bh * HDIM * VPAD;
    for (int idx = tid; idx < 208 * 4; idx += 416) {
        int row = idx >> 2, slot = idx & 3;
        int4 v = make_int4(0, 0, 0, 0);
        if (row < NTOK) v = *(const int4*)(qg + row * HDIM + slot * 16);
        *(int4*)&sQ[row * QSTR + slot * 4] = v;
    }
    for (int idx = tid; idx < 200 * 4; idx += 416) {
        int row = idx >> 2, slot = idx & 3;
        int4 v = make_int4(0, 0, 0, 0);
        if (row < NTOK) v = *(const int4*)(kg + row * HDIM + slot * 16);
        *(int4*)&sK[row * QSTR + slot * 4] = v;
    }
    for (int idx = tid; idx < 64 * 13; idx += 416) {
        int row = idx / 13, slot = idx % 13;
        *(int4*)&sVT[row * SSTR + slot * 4] = *(const int4*)(vg + row * VPAD + slot * 16);
    }
    for (int idx = tid; idx < 208 * 6; idx += 416)
        sS[(idx / 6) * SSTR + 50 + (idx % 6)] = 0;
    for (int i = tid; i < 27 * 64; i += 416) {
        int r = i >> 6, c = i & 63;
        sRhT[c * 28 + r] = rph[i];
        sRwT[c * 28 + r] = rpw[i];
    }
    __syncthreads();

    float a0s = as[0];
    if (tid < NTOK) {
        int t = tid;
        int hh = t / WSZ, ww2 = t % WSZ;
        float ah[WSZ], aw[WSZ];
#pragma unroll
        for (int kk = 0; kk < WSZ; ++kk) { ah[kk] = 0.f; aw[kk] = 0.f; }
#pragma unroll
        for (int j = 0; j < 16; ++j) {
            int packed = sQ[t * QSTR + j];
#pragma unroll
            for (int b = 0; b < 4; ++b) {
                int c = j * 4 + b;
                float qv = (float)((packed << (24 - 8 * b)) >> 24);
                const float* ph = &sRhT[c * 28 + hh + 13];
                const float* pw = &sRwT[c * 28 + ww2 + 13];
#pragma unroll
                for (int kk = 0; kk < WSZ; ++kk) {
                    ah[kk] += qv * ph[-kk];
                    aw[kk] += qv * pw[-kk];
                }
            }
        }
#pragma unroll
        for (int kk = 0; kk < WSZ; ++kk) {
            sRel[t * 28 + kk]      = ah[kk] * a0s;
            sRel[t * 28 + 14 + kk] = aw[kk] * a0s;
        }
    }
    __syncthreads();

    float c_qk = 0.125f * a0s * as[1];
    float inva3 = 1.0f / as[3];
    float c_av = as[3] * as[2];
    float inva5 = 1.0f / as[5];
    int wi = bh / NHEAD, head = bh % NHEAD;
    int wrem = wi % 25, wb = wi / 25, wwr = wrem / 5, wwc = wrem % 5;
    char* sSb = (char*)sS;

    {
        int s = wid;
        int m_lo = s * 16 + lrow, m_hi = m_lo + 8;
        int acc[25][4];
#pragma unroll
        for (int t = 0; t < 25; ++t) { acc[t][0]=acc[t][1]=acc[t][2]=acc[t][3]=0; }
#pragma unroll
        for (int kc = 0; kc < 2; ++kc) {
            int kb = kc * 8;
            int a0 = sQ[m_lo * QSTR + kb + lk];
            int a1 = sQ[m_hi * QSTR + kb + lk];
            int a2 = sQ[m_lo * QSTR + kb + 4 + lk];
            int a3 = sQ[m_hi * QSTR + kb + 4 + lk];
#pragma unroll
            for (int t = 0; t < 25; ++t) {
                int col = t * 8 + lrow;
                mma_s8(acc[t][0], acc[t][1], acc[t][2], acc[t][3],
                       a0, a1, a2, a3, sK[col * QSTR + kb + lk], sK[col * QSTR + kb + 4 + lk]);
            }
        }
        bool vlo = (m_lo < NTOK), vhi = (m_hi < NTOK);
        const float* rlo_p = &sRel[m_lo * 28];
        const float* rhi_p = &sRel[m_hi * 28];
#pragma unroll
        for (int t = 0; t < 25; ++t) {
#pragma unroll
            for (int r = 0; r < 4; ++r) {
                int n = t * 8 + lk * 2 + (r & 1);
                bool vm = (r < 2) ? vlo : vhi;
                float f;
                if (n < NTOK && vm) {
                    const float* rp = (r < 2) ? rlo_p : rhi_p;
                    f = (float)acc[t][r] * c_qk + rp[n / WSZ] + rp[14 + n % WSZ];
                } else f = -1e30f;
                acc[t][r] = __float_as_int(f);
            }
        }
        float mx0 = -1e30f, mx1 = -1e30f;
#pragma unroll
        for (int t = 0; t < 25; ++t) {
            mx0 = fmaxf(mx0, fmaxf(__int_as_float(acc[t][0]), __int_as_float(acc[t][1])));
            mx1 = fmaxf(mx1, fmaxf(__int_as_float(acc[t][2]), __int_as_float(acc[t][3])));
        }
        mx0 = fmaxf(mx0, __shfl_xor_sync(~0u, mx0, 1)); mx0 = fmaxf(mx0, __shfl_xor_sync(~0u, mx0, 2));
        mx1 = fmaxf(mx1, __shfl_xor_sync(~0u, mx1, 1)); mx1 = fmaxf(mx1, __shfl_xor_sync(~0u, mx1, 2));
        float s0 = 0.f, s1 = 0.f;
#pragma unroll
        for (int t = 0; t < 25; ++t) {
            float e0 = __expf(__int_as_float(acc[t][0]) - mx0);
            float e1 = __expf(__int_as_float(acc[t][1]) - mx0);
            float e2 = __expf(__int_as_float(acc[t][2]) - mx1);
            float e3 = __expf(__int_as_float(acc[t][3]) - mx1);
            acc[t][0] = __float_as_int(e0); acc[t][1] = __float_as_int(e1);
            acc[t][2] = __float_as_int(e2); acc[t][3] = __float_as_int(e3);
            s0 += e0 + e1; s1 += e2 + e3;
        }
        s0 += __shfl_xor_sync(~0u, s0, 1); s0 += __shfl_xor_sync(~0u, s0, 2);
        s1 += __shfl_xor_sync(~0u, s1, 1); s1 += __shfl_xor_sync(~0u, s1, 2);
        float r0 = inva3 / s0, r1 = inva3 / s1;
#pragma unroll
        for (int t = 0; t < 25; ++t) {
            int v00 = q8i(__int_as_float(acc[t][0]), r0);
            int v01 = q8i(__int_as_float(acc[t][1]), r0);
            int v10 = q8i(__int_as_float(acc[t][2]), r1);
            int v11 = q8i(__int_as_float(acc[t][3]), r1);
            *(unsigned short*)(sSb + m_lo * (SSTR * 4) + t * 8 + lk * 2) =
                (unsigned short)((v00 & 0xFF) | ((v01 & 0xFF) << 8));
            *(unsigned short*)(sSb + m_hi * (SSTR * 4) + t * 8 + lk * 2) =
                (unsigned short)((v10 & 0xFF) | ((v11 & 0xFF) << 8));
        }
        __syncwarp();
        int oacc[8][4];
#pragma unroll
        for (int j = 0; j < 8; ++j) { oacc[j][0]=oacc[j][1]=oacc[j][2]=oacc[j][3]=0; }
#pragma unroll
        for (int kc = 0; kc < 7; ++kc) {
            int kb = kc * 8;
            int a0 = sS[m_lo * SSTR + kb + lk];
            int a1 = sS[m_hi * SSTR + kb + lk];
            int a2 = sS[m_lo * SSTR + kb + 4 + lk];
            int a3 = sS[m_hi * SSTR + kb + 4 + lk];
#pragma unroll
            for (int j = 0; j < 8; ++j) {
                int col = j * 8 + lrow;
                mma_s8(oacc[j][0], oacc[j][1], oacc[j][2], oacc[j][3],
                       a0, a1, a2, a3, sVT[col * SSTR + kb + lk], sVT[col * SSTR + kb + 4 + lk]);
            }
        }
        int rlo = wwr * WSZ + m_lo / WSZ, clo = wwc * WSZ + m_lo % WSZ;
        int rhi = wwr * WSZ + m_hi / WSZ, chi = wwc * WSZ + m_hi % WSZ;
        bool oklo = vlo && rlo < HH && clo < WW;
        bool okhi = vhi && rhi < HH && chi < WW;
        size_t plo = (((size_t)(wb * HH + rlo)) * WW + clo) * DIMC + head * HDIM;
        size_t phi = (((size_t)(wb * HH + rhi)) * WW + chi) * DIMC + head * HDIM;
#pragma unroll
        for (int j = 0; j < 8; ++j) {
            int n = j * 8 + lk * 2;
            if (oklo) {
                int v0 = q8i((float)oacc[j][0] * c_av, inva5);
                int v1 = q8i((float)oacc[j][1] * c_av, inva5);
                *(unsigned short*)(g_ov + plo + n) =
                    (unsigned short)((v0 & 0xFF) | ((v1 & 0xFF) << 8));
            }
            if (okhi) {
                int v0 = q8i((float)oacc[j][2] * c_av, inva5);
                int v1 = q8i((float)oacc[j][3] * c_av, inva5);
                *(unsigned short*)(g_ov + phi + n) =
                    (unsigned short)((v0 & 0xFF) | ((v1 & 0xFF) << 8));
            }
        }
    }
}

// ------------------------------ int8 IMMA GEMM (cp.async, 3-stage, 64B K) ---
#define GEMM_SMEM 61440

template <typename Epi>
__global__ void __launch_bounds__(256)
gemm_i8(int aid, int bid, int Kints, Epi epi) {
    extern __shared__ int gsm[];
    const int8_t* Ab = srcA(aid);
    const int8_t* Bb = srcB(bid);
    int bm = blockIdx.y * 128, bn = blockIdx.x * 128;
    int tid = threadIdx.x;
    int lane = tid & 31, wid = tid >> 5;
    int wm = wid >> 2, wn = wid & 3;
    int lrow = lane >> 2, lk = lane & 3;
    int srow = tid >> 2;
    int slot = tid & 3;

    uint32_t sbase = (uint32_t)__cvta_generic_to_shared(gsm);
    const int* Abase = (const int*)Ab + (size_t)(bm + srow) * Kints + slot * 4;
    const int* Bbase = (const int*)Bb + (size_t)(bn + srow) * Kints + slot * 4;
    size_t rowskip = (size_t)64 * Kints;
    uint32_t a_off = sbase + srow * 80 + slot * 16;
    uint32_t b_off = sbase + 30720 + srow * 80 + slot * 16;

    int acc[4][4][4];
#pragma unroll
    for (int i = 0; i < 4; ++i)
#pragma unroll
        for (int j = 0; j < 4; ++j)
#pragma unroll
            for (int r = 0; r < 4; ++r) acc[i][j][r] = 0;

    auto load_tile = [&](int kt, int stg) {
        int k0 = kt * 16;
        const int* ga = Abase + k0;
        const int* gb = Bbase + k0;
        uint32_t ao = a_off + stg * 10240;
        uint32_t bo = b_off + stg * 10240;
        CP_ASYNC16(ao, ga);
        CP_ASYNC16(ao + 64 * 80, ga + rowskip);
        CP_ASYNC16(bo, gb);
        CP_ASYNC16(bo + 64 * 80, gb + rowskip);
        CP_COMMIT();
    };

    int nk = Kints >> 4;
    load_tile(0, 0);
    load_tile(1, 1);

    for (int kt = 0; kt < nk; ++kt) {
        CP_WAIT1();
        __syncthreads();
        int cur = kt - (kt / 3) * 3;
        const int* sAc = gsm + cur * 2560;
        const int* sBc = gsm + 7680 + cur * 2560;
#pragma unroll
        for (int kc = 0; kc < 2; ++kc) {
            int kb = kc * 8;
            int b0[4], b1[4];
#pragma unroll
            for (int j = 0; j < 4; ++j) {
                int col = wn * 32 + j * 8 + lrow;
                b0[j] = sBc[col * 20 + kb + lk];
                b1[j] = sBc[col * 20 + kb + 4 + lk];
            }
#pragma unroll
            for (int i = 0; i < 4; ++i) {
                int r0 = wm * 64 + i * 16 + lrow;
                int a0 = sAc[r0 * 20 + kb + lk];
                int a1 = sAc[(r0 + 8) * 20 + kb + lk];
                int a2 = sAc[r0 * 20 + kb + 4 + lk];
                int a3 = sAc[(r0 + 8) * 20 + kb + 4 + lk];
#pragma unroll
                for (int j = 0; j < 4; ++j)
                    mma_s8(acc[i][j][0], acc[i][j][1], acc[i][j][2], acc[i][j][3],
                           a0, a1, a2, a3, b0[j], b1[j]);
            }
        }
        if (kt + 2 < nk) {
            int stg = kt + 2;
            stg -= (stg / 3) * 3;
            load_tile(kt + 2, stg);
        }
    }

    epi.prep();
#pragma unroll
    for (int i = 0; i < 4; ++i) {
        int m0 = bm + wm * 64 + i * 16 + lrow;
#pragma unroll
        for (int j = 0; j < 4; ++j) {
            int n0 = bn + wn * 32 + j * 8 + lk * 2;
            epi.pair(acc[i][j][0], acc[i][j][1], m0, n0);
            epi.pair(acc[i][j][2], acc[i][j][3], m0 + 8, n0);
        }
    }
}

// ------------------------------ GEMM epilogues (paired, n even) -------------
struct EpiQKV {
    const float* as; const float* ws; const float* qb;
    float s1, inv0, inv1, inv2;
    __device__ void prep() {
        s1 = as[4] * ws[0];
        inv0 = 1.0f / as[0]; inv1 = 1.0f / as[1]; inv2 = 1.0f / as[2];
    }
    __device__ void pair(int acc0, int acc1, int m, int n) const {
        float f0 = (float)acc0 * s1 + qb[n];
        float f1 = (float)acc1 * s1 + qb[n + 1];
        int qi = (n >= 1536) ? 2 : (n >= 768 ? 1 : 0);
        int rem = n - qi * 768;
        int head = rem >> 6, d = rem & 63;           // d even
        int b = m >> 12, r = (m >> 6) & 63, c = m & 63;
        int wr = r / WSZ, lr = r - wr * WSZ;
        int wc = c / WSZ, lc = c - wc * WSZ;
        int wi = b * 25 + wr * 5 + wc;
        int t = lr * WSZ + lc;
        int bh = wi * NHEAD + head;
        if (qi == 0) {
            int v0 = q8i(f0, inv0), v1 = q8i(f1, inv0);
            *(unsigned short*)(g_q + ((size_t)bh * NTOK + t) * HDIM + d) =
                (unsigned short)((v0 & 0xFF) | ((v1 & 0xFF) << 8));
        } else if (qi == 1) {
            int v0 = q8i(f0, inv1), v1 = q8i(f1, inv1);
            *(unsigned short*)(g_k + ((size_t)bh * NTOK + t) * HDIM + d) =
                (unsigned short)((v0 & 0xFF) | ((v1 & 0xFF) << 8));
        } else {
            g_vT[((size_t)bh * HDIM + d)     * VPAD + t] = fq8m(f0, inv2);
            g_vT[((size_t)bh * HDIM + d + 1) * VPAD + t] = fq8m(f1, inv2);
        }
    }
};
struct EpiProj {
    const float* as; const float* ws; const float* pb; const float* x;
    float s1;
    __device__ void prep() { s1 = as[5] * ws[1]; }
    __device__ void pair(int acc0, int acc1, int m, int n) const {
        size_t idx = (size_t)m * DIMC + n;
        float2 xv = *(const float2*)(x + idx);
        float2 o;
        o.x = xv.x + (float)acc0 * s1 + pb[n];
        o.y = xv.y + (float)acc1 * s1 + pb[n + 1];
        *(float2*)(g_xres + idx) = o;
    }
};
struct EpiL1 {
    const float* as; const float* ws; const float* lb;
    float s1, inv7;
    __device__ void prep() { s1 = as[6] * ws[2]; inv7 = 1.0f / as[7]; }
    __device__ float gelu(float f) const {
        float xx = f * 0.70710678118654752f;
        float ax = fabsf(xx);
        float t = __fdividef(1.0f, 1.0f + 0.3275911f * ax);
        float poly = t * (0.254829592f + t * (-0.284496736f + t * (1.421413741f +
                     t * (-1.453152027f + t * 1.061405429f))));
        float erfv = 1.0f - poly * __expf(-xx * xx);
        erfv = copysignf(erfv, xx);
        return 0.5f * f * (1.0f + erfv);
    }
    __device__ void pair(int acc0, int acc1, int m, int n) const {
        float f0 = (float)acc0 * s1 + lb[n];
        float f1 = (float)acc1 * s1 + lb[n + 1];
        int v0 = q8i(gelu(f0), inv7);
        int v1 = q8i(gelu(f1), inv7);
        *(unsigned short*)(g_hbuf + (size_t)m * MLPD + n) =
            (unsigned short)((v0 & 0xFF) | ((v1 & 0xFF) << 8));
    }
};
struct EpiL2 {
    const float* as; const float* ws; const float* lb; float* out;
    float s1;
    __device__ void prep() { s1 = as[7] * ws[3]; }
    __device__ void pair(int acc0, int acc1, int m, int n) const {
        size_t idx = (size_t)m * DIMC + n;
        float2 rv = *(const float2*)(g_xres + idx);
        float2 o;
        o.x = rv.x + (float)acc0 * s1 + lb[n];
        o.y = rv.y + (float)acc1 * s1 + lb[n + 1];
        *(float2*)(out + idx) = o;
    }
};

// ------------------------------ launch --------------------------------------
extern "C" void kernel_launch(void* const* d_in, const int* in_sizes, int n_in,
                              void* d_out, int out_size) {
    const float* x      = (const float*)d_in[0];
    const float* ln1_w  = (const float*)d_in[1];
    const float* ln1_b  = (const float*)d_in[2];
    const float* ln2_w  = (const float*)d_in[3];
    const float* ln2_b  = (const float*)d_in[4];
    const float* qkv_w  = (const float*)d_in[5];
    const float* qkv_b  = (const float*)d_in[6];
    const float* proj_w = (const float*)d_in[7];
    const float* proj_b = (const float*)d_in[8];
    const float* lin1_w = (const float*)d_in[9];
    const float* lin1_b = (const float*)d_in[10];
    const float* lin2_w = (const float*)d_in[11];
    const float* lin2_b = (const float*)d_in[12];
    const float* rph    = (const float*)d_in[13];
    const float* rpw    = (const float*)d_in[14];
    const float* asc    = (const float*)d_in[15];
    const float* wsc    = (const float*)d_in[16];
    float* out = (float*)d_out;

    cudaFuncSetAttribute(attn_fused_kernel, cudaFuncAttributeMaxDynamicSharedMemorySize, ATT_SMEM);
    cudaFuncSetAttribute(gemm_i8<EpiQKV>,  cudaFuncAttributeMaxDynamicSharedMemorySize, GEMM_SMEM);
    cudaFuncSetAttribute(gemm_i8<EpiProj>, cudaFuncAttributeMaxDynamicSharedMemorySize, GEMM_SMEM);
    cudaFuncSetAttribute(gemm_i8<EpiL1>,   cudaFuncAttributeMaxDynamicSharedMemorySize, GEMM_SMEM);
    cudaFuncSetAttribute(gemm_i8<EpiL2>,   cudaFuncAttributeMaxDynamicSharedMemorySize, GEMM_SMEM);

    quant_w_all<<<(QW_TOT + 255) / 256, 256>>>(qkv_w, proj_w, lin1_w, lin2_w, wsc);

    ln1_kernel<<<PIX / 8, 256>>>(x, ln1_w, ln1_b, asc);
    pad_qkv_kernel<<<NWIN, 256>>>(qkv_b, asc);

    gemm_i8<EpiQKV><<<dim3(18, 128), 256, GEMM_SMEM>>>(0, 0, DIMC / 4,
                                                       EpiQKV{asc, wsc, qkv_b});

    attn_fused_kernel<<<BHD, 416, ATT_SMEM>>>(rph, rpw, asc);

    gemm_i8<EpiProj><<<dim3(6, 128), 256, GEMM_SMEM>>>(3, 3, DIMC / 4,
                                                       EpiProj{asc, wsc, proj_b, x});

    ln2_kernel<<<PIX / 8, 256>>>(ln2_w, ln2_b, asc);

    gemm_i8<EpiL1><<<dim3(24, 128), 256, GEMM_SMEM>>>(4, 4, DIMC / 4,
                                                      EpiL1{asc, wsc, lin1_b});
    gemm_i8<EpiL2><<<dim3(6, 128), 256, GEMM_SMEM>>>(5, 5, MLPD / 4,
                                                     EpiL2{asc, wsc, lin2_b, out});
}